// round 14
// baseline (speedup 1.0000x reference)
#include <cuda_runtime.h>
#include <math.h>

#define N_NODES 10000
#define N_EDGES 160000
#define N_GRAPHS 64
#define FDIM 80
#define TDIM 5
#define F_OUT 16
#define N_LAYERS 4
#define D400 400
#define D1600 1600
#define D800000 800000

typedef unsigned long long ull;

// ---------------- scratch ----------------
__device__ float g_H0[D800000];
__device__ float g_A[N_NODES * D400];
__device__ float g_B[N_NODES * D400];
__device__ float g_AGG[N_NODES * D1600];
__device__ float g_TMP[D800000];
__device__ float g_Y[D800000];
__device__ float g_Wpk4[N_LAYERS * FDIM * 800];
__device__ int   g_degi[N_NODES];
__device__ float g_degf[N_NODES];
__device__ float g_c1[N_NODES];
__device__ float g_c2[N_NODES];
__device__ int   g_off[N_NODES + 1];
__device__ int   g_cursor[N_NODES];
__device__ int   g_csr[N_EDGES];
__device__ double g_bnsum[FDIM];
__device__ double g_bnsq[FDIM];
__device__ float g_bns[FDIM];
__device__ float g_bnt[FDIM];
__device__ float g_avgld;
__device__ float g_LXC[N_NODES * 40];
__device__ float g_pooled[N_GRAPHS * 40];
__device__ int   g_gcnt[N_GRAPHS];
__device__ int   g_mode;

__device__ __forceinline__ int rd_idx(const void* p, int i) {
    return g_mode ? ((const int*)p)[i] : (int)((const long long*)p)[i];
}

// ---- packed f32x2 helpers ----
__device__ __forceinline__ void fma2(ull& d, ull a, ull b) {
    asm("fma.rn.f32x2 %0, %1, %2, %0;" : "+l"(d) : "l"(a), "l"(b));
}
__device__ __forceinline__ ull pack_dup(float w) {
    ull r;
    asm("mov.b64 %0, {%1, %1};" : "=l"(r) : "f"(w));
    return r;
}
__device__ __forceinline__ float2 unpack2(ull v) {
    float2 f;
    asm("mov.b64 {%0, %1}, %2;" : "=f"(f.x), "=f"(f.y) : "l"(v));
    return f;
}

__device__ __forceinline__ float4 bn_relu4(float4 v, int f0) {
    float4 s = *(const float4*)&g_bns[f0];
    float4 t = *(const float4*)&g_bnt[f0];
    v.x = fmaxf(v.x * s.x + t.x, 0.f);
    v.y = fmaxf(v.y * s.y + t.y, 0.f);
    v.z = fmaxf(v.z * s.z + t.z, 0.f);
    v.w = fmaxf(v.w * s.w + t.w, 0.f);
    return v;
}

// ---------------- zero + dtype detect ----------------
__global__ void k_zero(const void* ei) {
    int i = blockIdx.x * blockDim.x + threadIdx.x;
    if (blockIdx.x == 0 && threadIdx.x < 32) {
        long long v = ((const long long*)ei)[threadIdx.x];
        unsigned bad = __ballot_sync(0xffffffffu, v < 0 || v >= N_NODES);
        if (threadIdx.x == 0) g_mode = bad ? 1 : 0;
    }
    if (i < N_NODES) g_degi[i] = 0;
    if (i < N_GRAPHS) g_gcnt[i] = 0;
    if (i < N_GRAPHS * 40) g_pooled[i] = 0.f;
}

// ---------------- degree + graph-count ----------------
__global__ void k_deg(const void* __restrict__ ei, const void* __restrict__ batch) {
    __shared__ int cnt[N_GRAPHS];
    int tid = threadIdx.x;
    if (tid < N_GRAPHS) cnt[tid] = 0;
    __syncthreads();
    int e = blockIdx.x * blockDim.x + tid;
    if (e < N_EDGES) {
        int s = rd_idx(ei, e);
        int d = rd_idx(ei, N_EDGES + e);
        if ((unsigned)s < N_NODES && (unsigned)d < N_NODES)
            atomicAdd(&g_degi[d], 1);
    }
    if (e < N_NODES) {
        int g = rd_idx(batch, e);
        if ((unsigned)g < N_GRAPHS) atomicAdd(&cnt[g], 1);
    }
    __syncthreads();
    if (tid < N_GRAPHS && cnt[tid] > 0) atomicAdd(&g_gcnt[tid], cnt[tid]);
}

// ---------------- scan + avg_log_deg + coef ----------------
__global__ void k_scan() {
    __shared__ int part[1024];
    __shared__ double dsum[1024];
    __shared__ float s_avg;
    int tid = threadIdx.x;
    const int PER = 10;
    int local[PER];
    int s = 0;
    int base = tid * PER;
    #pragma unroll
    for (int i = 0; i < PER; i++) {
        int idx = base + i;
        int v = (idx < N_NODES) ? g_degi[idx] : 0;
        local[i] = v;
        s += v;
    }
    part[tid] = s;
    __syncthreads();
    for (int ofs = 1; ofs < 1024; ofs <<= 1) {
        int v = 0;
        if (tid >= ofs) v = part[tid - ofs];
        __syncthreads();
        part[tid] += v;
        __syncthreads();
    }
    int run = part[tid] - s;
    #pragma unroll
    for (int i = 0; i < PER; i++) {
        int idx = base + i;
        if (idx < N_NODES) {
            g_off[idx] = run;
            g_cursor[idx] = run;
            g_degf[idx] = (float)local[i];
            run += local[i];
        }
    }
    if (tid == 1023) g_off[N_NODES] = part[1023];
    double ld = 0.0;
    #pragma unroll
    for (int i = 0; i < PER; i++) {
        int idx = base + i;
        if (idx < N_NODES) ld += log((double)local[i] + 1.0);
    }
    dsum[tid] = ld;
    __syncthreads();
    for (int ofs = 512; ofs > 0; ofs >>= 1) {
        if (tid < ofs) dsum[tid] += dsum[tid + ofs];
        __syncthreads();
    }
    if (tid == 0) {
        float a = (float)(dsum[0] / (double)N_NODES);
        g_avgld = a;
        s_avg = a;
    }
    __syncthreads();
    float avg = s_avg;
    #pragma unroll
    for (int i = 0; i < PER; i++) {
        int idx = base + i;
        if (idx < N_NODES) {
            float logd = logf(fmaxf((float)local[i], 1.f) + 1.f);
            g_c1[idx] = logd / avg;
            g_c2[idx] = avg / logd;
        }
    }
}

__global__ void k_scatter(const void* __restrict__ ei) {
    int e = blockIdx.x * blockDim.x + threadIdx.x;
    if (e >= N_EDGES) return;
    int srcv = rd_idx(ei, e);
    int d    = rd_idx(ei, N_EDGES + e);
    if ((unsigned)srcv >= N_NODES || (unsigned)d >= N_NODES) return;
    int pos = atomicAdd(&g_cursor[d], 1);
    if ((unsigned)pos < N_EDGES) g_csr[pos] = srcv;
}

// ---------------- pre-lin ----------------
__global__ void k_prelin(const float* __restrict__ x,
                         const float* __restrict__ W,
                         const float* __restrict__ b) {
    int i = blockIdx.x * blockDim.x + threadIdx.x;
    if (i >= N_NODES * FDIM) return;
    int n = i / FDIM, f = i % FDIM;
    g_H0[i] = x[n * 2] * W[f] + b[f];
}

// ---------------- weight repack ----------------
__global__ void k_repack4(const float* __restrict__ preW) {
    int i = blockIdx.x * blockDim.x + threadIdx.x;
    if (i >= N_LAYERS * FDIM * 800) return;
    int l = i / (FDIM * 800);
    int r = i % (FDIM * 800);
    int f = r / 800, j = r % 800;
    int isA = (j < 400);
    int jj = isA ? j : j - 400;
    int t = jj / FDIM, o = jj % FDIM;
    g_Wpk4[i] = preW[l * (TDIM * 160 * FDIM) + t * 160 * FDIM + (isA ? f : FDIM + f) * FDIM + o];
}

// ---------------- gemmAB: pipelined reg-prefetch, BN-on-store, 8x4 FFMA2 ----------------
__global__ void __launch_bounds__(256, 3)
k_gemm(const float* __restrict__ Ain, const float* __restrict__ Bw,
       const float* __restrict__ bias, int bnflag) {
    __shared__ __align__(16) float sH[16][128];
    __shared__ __align__(16) float sW[16][64];
    int bm = blockIdx.y * 128, bn = blockIdx.x * 64;
    int tid = threadIdx.x;
    if (blockIdx.x == 0 && blockIdx.y == 0 && tid < 160) {
        if (tid < 80) g_bnsum[tid] = 0.0;
        else          g_bnsq[tid - 80] = 0.0;
    }
    int tx = tid & 15, ty = tid >> 4;
    int arow0 = tid >> 2,            ac40 = (tid & 3) * 4;
    int arow1 = (tid + 256) >> 2,    ac41 = ((tid + 256) & 3) * 4;
    int wkrow = tid >> 4,            wc4  = (tid & 15) * 4;
    int m0 = bm + arow0, m1 = bm + arow1;
    int jw = bn + wc4;

    ull acc[4][4];
    #pragma unroll
    for (int i = 0; i < 4; i++)
        #pragma unroll
        for (int j = 0; j < 4; j++) acc[i][j] = 0ull;

    float4 rA0 = make_float4(0.f, 0.f, 0.f, 0.f);
    float4 rA1 = make_float4(0.f, 0.f, 0.f, 0.f);
    float4 rW  = make_float4(0.f, 0.f, 0.f, 0.f);
    if (m0 < N_NODES) rA0 = *(const float4*)&Ain[m0 * FDIM + ac40];
    if (m1 < N_NODES) rA1 = *(const float4*)&Ain[m1 * FDIM + ac41];
    if (jw < 800)     rW  = *(const float4*)&Bw[wkrow * 800 + jw];

    #pragma unroll
    for (int kt = 0; kt < 5; kt++) {
        float4 v0 = rA0, v1 = rA1;
        if (bnflag) {
            if (m0 < N_NODES) v0 = bn_relu4(v0, kt * 16 + ac40);
            if (m1 < N_NODES) v1 = bn_relu4(v1, kt * 16 + ac41);
        }
        sH[ac40][arow0] = v0.x; sH[ac40 + 1][arow0] = v0.y;
        sH[ac40 + 2][arow0] = v0.z; sH[ac40 + 3][arow0] = v0.w;
        sH[ac41][arow1] = v1.x; sH[ac41 + 1][arow1] = v1.y;
        sH[ac41 + 2][arow1] = v1.z; sH[ac41 + 3][arow1] = v1.w;
        *(float4*)&sW[wkrow][wc4] = rW;
        __syncthreads();
        if (kt < 4) {
            rA0 = make_float4(0.f, 0.f, 0.f, 0.f);
            rA1 = make_float4(0.f, 0.f, 0.f, 0.f);
            rW  = make_float4(0.f, 0.f, 0.f, 0.f);
            if (m0 < N_NODES) rA0 = *(const float4*)&Ain[m0 * FDIM + (kt + 1) * 16 + ac40];
            if (m1 < N_NODES) rA1 = *(const float4*)&Ain[m1 * FDIM + (kt + 1) * 16 + ac41];
            if (jw < 800)     rW  = *(const float4*)&Bw[((kt + 1) * 16 + wkrow) * 800 + jw];
        }
        #pragma unroll
        for (int k = 0; k < 16; k++) {
            ulonglong2 pA = *(ulonglong2*)&sH[k][ty * 8];
            ulonglong2 pB = *(ulonglong2*)&sH[k][ty * 8 + 4];
            ull av[4] = {pA.x, pA.y, pB.x, pB.y};
            float4 b = *(float4*)&sW[k][tx * 4];
            ull bd[4] = {pack_dup(b.x), pack_dup(b.y), pack_dup(b.z), pack_dup(b.w)};
            #pragma unroll
            for (int i = 0; i < 4; i++)
                #pragma unroll
                for (int j = 0; j < 4; j++) fma2(acc[i][j], av[i], bd[j]);
        }
        __syncthreads();
    }
    #pragma unroll
    for (int i = 0; i < 4; i++) {
        #pragma unroll
        for (int j = 0; j < 4; j++) {
            int col = bn + tx * 4 + j;
            if (col >= 800) continue;
            float2 c = unpack2(acc[i][j]);
            #pragma unroll
            for (int h = 0; h < 2; h++) {
                int m = bm + ty * 8 + i * 2 + h;
                if (m >= N_NODES) continue;
                float cv = h ? c.y : c.x;
                if (col < 400) g_A[m * 400 + col] = cv + bias[col];
                else           g_B[m * 400 + col - 400] = cv;
            }
        }
    }
}

// ---------------- lin gemm: pipelined + fused BN stats ----------------
__global__ void __launch_bounds__(256, 3)
k_gemmLin(const float* __restrict__ Ain, const float* __restrict__ Bw,
          const float* __restrict__ bias) {
    __shared__ __align__(16) float sH[16][128];
    __shared__ __align__(16) float sW[16][64];
    __shared__ float sS[16][64];
    __shared__ float sQ[16][64];
    int bm = blockIdx.y * 128, bn = blockIdx.x * 64;
    int tid = threadIdx.x;
    int tx = tid & 15, ty = tid >> 4;
    int arow0 = tid >> 2,            ac40 = (tid & 3) * 4;
    int arow1 = (tid + 256) >> 2,    ac41 = ((tid + 256) & 3) * 4;
    int wkrow = tid >> 4,            wc4  = (tid & 15) * 4;
    int m0 = bm + arow0, m1 = bm + arow1;
    int jw = bn + wc4;

    ull acc[4][4];
    #pragma unroll
    for (int i = 0; i < 4; i++)
        #pragma unroll
        for (int j = 0; j < 4; j++) acc[i][j] = 0ull;

    float4 rA0 = make_float4(0.f, 0.f, 0.f, 0.f);
    float4 rA1 = make_float4(0.f, 0.f, 0.f, 0.f);
    float4 rW  = make_float4(0.f, 0.f, 0.f, 0.f);
    if (m0 < N_NODES) rA0 = *(const float4*)&Ain[m0 * FDIM + ac40];
    if (m1 < N_NODES) rA1 = *(const float4*)&Ain[m1 * FDIM + ac41];
    if (jw < FDIM)    rW  = *(const float4*)&Bw[wkrow * FDIM + jw];

    #pragma unroll
    for (int kt = 0; kt < 5; kt++) {
        sH[ac40][arow0] = rA0.x; sH[ac40 + 1][arow0] = rA0.y;
        sH[ac40 + 2][arow0] = rA0.z; sH[ac40 + 3][arow0] = rA0.w;
        sH[ac41][arow1] = rA1.x; sH[ac41 + 1][arow1] = rA1.y;
        sH[ac41 + 2][arow1] = rA1.z; sH[ac41 + 3][arow1] = rA1.w;
        *(float4*)&sW[wkrow][wc4] = rW;
        __syncthreads();
        if (kt < 4) {
            rA0 = make_float4(0.f, 0.f, 0.f, 0.f);
            rA1 = make_float4(0.f, 0.f, 0.f, 0.f);
            rW  = make_float4(0.f, 0.f, 0.f, 0.f);
            if (m0 < N_NODES) rA0 = *(const float4*)&Ain[m0 * FDIM + (kt + 1) * 16 + ac40];
            if (m1 < N_NODES) rA1 = *(const float4*)&Ain[m1 * FDIM + (kt + 1) * 16 + ac41];
            if (jw < FDIM)    rW  = *(const float4*)&Bw[((kt + 1) * 16 + wkrow) * FDIM + jw];
        }
        #pragma unroll
        for (int k = 0; k < 16; k++) {
            ulonglong2 pA = *(ulonglong2*)&sH[k][ty * 8];
            ulonglong2 pB = *(ulonglong2*)&sH[k][ty * 8 + 4];
            ull av[4] = {pA.x, pA.y, pB.x, pB.y};
            float4 b = *(float4*)&sW[k][tx * 4];
            ull bd[4] = {pack_dup(b.x), pack_dup(b.y), pack_dup(b.z), pack_dup(b.w)};
            #pragma unroll
            for (int i = 0; i < 4; i++)
                #pragma unroll
                for (int j = 0; j < 4; j++) fma2(acc[i][j], av[i], bd[j]);
        }
        __syncthreads();
    }
    float cs[4] = {0.f, 0.f, 0.f, 0.f};
    float cq[4] = {0.f, 0.f, 0.f, 0.f};
    #pragma unroll
    for (int i = 0; i < 4; i++) {
        #pragma unroll
        for (int j = 0; j < 4; j++) {
            int col = bn + tx * 4 + j;
            if (col >= FDIM) continue;
            float2 c = unpack2(acc[i][j]);
            #pragma unroll
            for (int h = 0; h < 2; h++) {
                int m = bm + ty * 8 + i * 2 + h;
                if (m >= N_NODES) continue;
                float cv = (h ? c.y : c.x) + bias[col];
                g_Y[m * FDIM + col] = cv;
                cs[j] += cv;
                cq[j] += cv * cv;
            }
        }
    }
    #pragma unroll
    for (int j = 0; j < 4; j++) {
        sS[ty][tx * 4 + j] = cs[j];
        sQ[ty][tx * 4 + j] = cq[j];
    }
    __syncthreads();
    if (tid < 64) {
        int col = bn + tid;
        if (col < FDIM) {
            float S = 0.f, Q = 0.f;
            #pragma unroll
            for (int r = 0; r < 16; r++) { S += sS[r][tid]; Q += sQ[r][tid]; }
            atomicAdd(&g_bnsum[col], (double)S);
            atomicAdd(&g_bnsq[col], (double)Q);
        }
    }
}

// ---------------- BN coef ----------------
__global__ void k_bncoef(const float* __restrict__ gamma, const float* __restrict__ beta) {
    int f = threadIdx.x;
    if (f >= FDIM) return;
    double mu = g_bnsum[f] / (double)N_NODES;
    double var = g_bnsq[f] / (double)N_NODES - mu * mu;
    double s = (double)gamma[f] / sqrt(var + 1e-5);
    g_bns[f] = (float)s;
    g_bnt[f] = (float)((double)beta[f] - mu * s);
}

// ---------------- edge stats ----------------
__global__ void k_edgestats() {
    int n = blockIdx.x;
    int d2 = threadIdx.x;
    if (d2 >= 200) return;
    int beg = g_off[n], end = g_off[n + 1];
    float2 s  = make_float2(0.f, 0.f);
    float2 sq = make_float2(0.f, 0.f);
    float2 mn = make_float2(INFINITY, INFINITY);
    float2 mx = make_float2(-INFINITY, -INFINITY);
    int i = beg;
    for (; i + 1 < end; i += 2) {
        int s0 = g_csr[i], s1 = g_csr[i + 1];
        float2 b0 = *(const float2*)&g_B[s0 * D400 + d2 * 2];
        float2 b1 = *(const float2*)&g_B[s1 * D400 + d2 * 2];
        s.x += b0.x + b1.x;       s.y += b0.y + b1.y;
        sq.x += b0.x * b0.x + b1.x * b1.x;
        sq.y += b0.y * b0.y + b1.y * b1.y;
        mn.x = fminf(mn.x, fminf(b0.x, b1.x)); mn.y = fminf(mn.y, fminf(b0.y, b1.y));
        mx.x = fmaxf(mx.x, fmaxf(b0.x, b1.x)); mx.y = fmaxf(mx.y, fmaxf(b0.y, b1.y));
    }
    if (i < end) {
        int s0 = g_csr[i];
        float2 b0 = *(const float2*)&g_B[s0 * D400 + d2 * 2];
        s.x += b0.x; s.y += b0.y;
        sq.x += b0.x * b0.x; sq.y += b0.y * b0.y;
        mn.x = fminf(mn.x, b0.x); mn.y = fminf(mn.y, b0.y);
        mx.x = fmaxf(mx.x, b0.x); mx.y = fmaxf(mx.y, b0.y);
    }
    float dg = g_degf[n];
    float cnt = fmaxf(dg, 1.f);
    float inv = 1.f / cnt;
    float2 a = *(const float2*)&g_A[n * D400 + d2 * 2];
    #pragma unroll
    for (int h = 0; h < 2; h++) {
        int d = d2 * 2 + h;
        float av  = h ? a.y : a.x;
        float sB  = h ? s.y : s.x;
        float sqB = h ? sq.y : sq.x;
        float mnB = h ? mn.y : mn.x;
        float mxB = h ? mx.y : mx.x;
        float mB = sB * inv;
        float mean, mnv, mxv, stdv;
        if (dg > 0.f) {
            mean = av + mB;
            mnv = av + mnB;
            mxv = av + mxB;
            stdv = sqrtf(fmaxf(sqB * inv - mB * mB, 0.f) + 1e-5f);
        } else {
            mean = 0.f; mnv = 0.f; mxv = 0.f;
            stdv = sqrtf(1e-5f);
        }
        int t = d / FDIM, f = d % FDIM;
        float* g = g_AGG + n * D1600 + t * 320;
        g[f] = mean;
        g[80 + f] = mnv;
        g[160 + f] = mxv;
        g[240 + f] = stdv;
    }
}

// ---------------- post (R12-proven: FFMA2, 128 threads, pack_dup weights) ----------------
__global__ void k_post3(const float* __restrict__ Hsrc, int bnflag,
                        const float* __restrict__ postW,
                        const float* __restrict__ postb) {
    __shared__ __align__(16) float sA[32][128];
    __shared__ __align__(16) float sW[3][32][16];
    __shared__ __align__(16) float sW0[16][16];
    int t  = blockIdx.y;
    int n0 = blockIdx.x * 128;
    int tid = threadIdx.x;
    int o0 = (tid & 7) * 2;
    int ny = tid >> 3;
    const float* W = postW + t * (1040 * 16);

    ull A0[2][4], A1[2][4], A2[2][4], A3[2][4];
    #pragma unroll
    for (int j = 0; j < 2; j++)
        #pragma unroll
        for (int p = 0; p < 4; p++) { A0[j][p] = A1[j][p] = A2[j][p] = A3[j][p] = 0ull; }

    for (int kt = 0; kt < 10; kt++) {
        #pragma unroll
        for (int it = 0; it < 8; it++) {
            int f4 = tid + it * 128;
            int n  = f4 >> 3;
            int kq = (f4 & 7) * 4;
            int nn = n0 + n;
            float4 v = make_float4(0.f, 0.f, 0.f, 0.f);
            if (nn < N_NODES)
                v = *(const float4*)&g_AGG[nn * 1600 + t * 320 + kt * 32 + kq];
            sA[kq][n] = v.x; sA[kq + 1][n] = v.y;
            sA[kq + 2][n] = v.z; sA[kq + 3][n] = v.w;
        }
        #pragma unroll
        for (int it = 0; it < 4; it++) {
            int idx = tid + it * 128;
            int k = idx >> 4, oo = idx & 15;
            int kg = kt * 32 + k;
            sW[0][k][oo] = W[(80  + kg) * 16 + oo];
            sW[1][k][oo] = W[(400 + kg) * 16 + oo];
            sW[2][k][oo] = W[(720 + kg) * 16 + oo];
        }
        __syncthreads();
        #pragma unroll
        for (int k = 0; k < 32; k++) {
            ulonglong2 pA = *(ulonglong2*)&sA[k][ny * 8];
            ulonglong2 pB = *(ulonglong2*)&sA[k][ny * 8 + 4];
            ull nv[4] = {pA.x, pA.y, pB.x, pB.y};
            float2 w1 = *(float2*)&sW[0][k][o0];
            float2 w2 = *(float2*)&sW[1][k][o0];
            float2 w3 = *(float2*)&sW[2][k][o0];
            ull w1x = pack_dup(w1.x), w1y = pack_dup(w1.y);
            ull w2x = pack_dup(w2.x), w2y = pack_dup(w2.y);
            ull w3x = pack_dup(w3.x), w3y = pack_dup(w3.y);
            #pragma unroll
            for (int p = 0; p < 4; p++) {
                fma2(A1[0][p], nv[p], w1x);  fma2(A1[1][p], nv[p], w1y);
                fma2(A2[0][p], nv[p], w2x);  fma2(A2[1][p], nv[p], w2y);
                fma2(A3[0][p], nv[p], w3x);  fma2(A3[1][p], nv[p], w3y);
            }
        }
        __syncthreads();
    }

    for (int kt = 0; kt < 5; kt++) {
        #pragma unroll
        for (int it = 0; it < 4; it++) {
            int f4 = tid + it * 128;
            int n  = f4 >> 2;
            int kq = (f4 & 3) * 4;
            int nn = n0 + n;
            float4 v = make_float4(0.f, 0.f, 0.f, 0.f);
            if (nn < N_NODES) {
                v = *(const float4*)&Hsrc[nn * FDIM + kt * 16 + kq];
                if (bnflag) v = bn_relu4(v, kt * 16 + kq);
            }
            sA[kq][n] = v.x; sA[kq + 1][n] = v.y;
            sA[kq + 2][n] = v.z; sA[kq + 3][n] = v.w;
        }
        #pragma unroll
        for (int it = 0; it < 2; it++) {
            int idx = tid + it * 128;
            int k = idx >> 4, oo = idx & 15;
            sW0[k][oo] = W[(kt * 16 + k) * 16 + oo];
        }
        __syncthreads();
        #pragma unroll
        for (int k = 0; k < 16; k++) {
            ulonglong2 pA = *(ulonglong2*)&sA[k][ny * 8];
            ulonglong2 pB = *(ulonglong2*)&sA[k][ny * 8 + 4];
            ull nv[4] = {pA.x, pA.y, pB.x, pB.y};
            float2 w0 = *(float2*)&sW0[k][o0];
            ull w0x = pack_dup(w0.x), w0y = pack_dup(w0.y);
            #pragma unroll
            for (int p = 0; p < 4; p++) {
                fma2(A0[0][p], nv[p], w0x);
                fma2(A0[1][p], nv[p], w0y);
            }
        }
        __syncthreads();
    }

    float bbx = postb[t * 16 + o0];
    float bby = postb[t * 16 + o0 + 1];
    #pragma unroll
    for (int p = 0; p < 4; p++) {
        float2 u0x = unpack2(A0[0][p]), u0y = unpack2(A0[1][p]);
        float2 u1x = unpack2(A1[0][p]), u1y = unpack2(A1[1][p]);
        float2 u2x = unpack2(A2[0][p]), u2y = unpack2(A2[1][p]);
        float2 u3x = unpack2(A3[0][p]), u3y = unpack2(A3[1][p]);
        int nnA = n0 + ny * 8 + p * 2;
        if (nnA < N_NODES) {
            float c1 = g_c1[nnA], c2 = g_c2[nnA];
            g_TMP[nnA * FDIM + t * 16 + o0]     = u0x.x + u1x.x + c1 * u2x.x + c2 * u3x.x + bbx;
            g_TMP[nnA * FDIM + t * 16 + o0 + 1] = u0y.x + u1y.x + c1 * u2y.x + c2 * u3y.x + bby;
        }
        int nnB = nnA + 1;
        if (nnB < N_NODES) {
            float c1 = g_c1[nnB], c2 = g_c2[nnB];
            g_TMP[nnB * FDIM + t * 16 + o0]     = u0x.y + u1x.y + c1 * u2x.y + c2 * u3x.y + bbx;
            g_TMP[nnB * FDIM + t * 16 + o0 + 1] = u0y.y + u1y.y + c1 * u2y.y + c2 * u3y.y + bby;
        }
    }
}

// ---------------- readout ----------------
__global__ void k_xc(const float* __restrict__ x) {
    int i = blockIdx.x * blockDim.x + threadIdx.x;
    if (i >= N_NODES * 40) return;
    int n = i / 40, d = i % 40;
    float sf = g_bns[d],      tf = g_bnt[d];
    float sb = g_bns[40 + d], tb = g_bnt[40 + d];
    float front  = fmaxf(g_Y[n * FDIM + d] * sf + tf, 0.f);
    float behind = fmaxf(g_Y[n * FDIM + 40 + d] * sb + tb, 0.f);
    float assign = x[n * 2 + 1];
    g_LXC[i] = logf(front * assign + behind + 1e-6f);
}

__global__ void k_logscore(const void* __restrict__ batch) {
    int n = blockIdx.x;
    int d = threadIdx.x;
    if (d >= 40) return;
    int beg = g_off[n], end = g_off[n + 1];
    float ls = 0.f;
    for (int i = beg; i < end; i++) {
        int srcv = g_csr[i];
        ls += g_LXC[srcv * 40 + d];
    }
    float val = expf(ls + g_LXC[n * 40 + d]);
    int g = rd_idx(batch, n);
    if ((unsigned)g >= N_GRAPHS) return;
    atomicAdd(&g_pooled[g * 40 + d], val);
}

__global__ void k_final(const float* __restrict__ mlW, const float* __restrict__ mlb,
                        const float* __restrict__ m1W, const float* __restrict__ m1b,
                        const float* __restrict__ m2W, const float* __restrict__ m2b,
                        float* __restrict__ out) {
    int g = threadIdx.x;
    if (g >= N_GRAPHS) return;
    float cnt = fmaxf((float)g_gcnt[g], 1.f);
    float p[40];
    #pragma unroll
    for (int d = 0; d < 40; d++) p[d] = g_pooled[g * 40 + d] / cnt;
    float xl = mlb[0];
    #pragma unroll
    for (int d = 0; d < 40; d++) xl += p[d] * mlW[d];
    float cv = m2b[0];
    for (int j = 0; j < 20; j++) {
        float h = m1b[j];
        #pragma unroll
        for (int d = 0; d < 40; d++) h += p[d] * m1W[d * 20 + j];
        h = 20.f - fmaxf(h, 0.f);
        cv += h * m2W[j];
    }
    out[g] = cv + xl;
}

// ---------------- launch ----------------
extern "C" void kernel_launch(void* const* d_in, const int* in_sizes, int n_in,
                              void* d_out, int out_size) {
    const float* x          = (const float*)d_in[0];
    const void*  ei         = d_in[1];
    const void*  batch      = d_in[2];
    const float* pre_lin_W  = (const float*)d_in[3];
    const float* pre_lin_b  = (const float*)d_in[4];
    const float* pre_W      = (const float*)d_in[5];
    const float* pre_b      = (const float*)d_in[6];
    const float* post_W     = (const float*)d_in[7];
    const float* post_b     = (const float*)d_in[8];
    const float* lin_W      = (const float*)d_in[9];
    const float* lin_b      = (const float*)d_in[10];
    const float* bn_gamma   = (const float*)d_in[11];
    const float* bn_beta    = (const float*)d_in[12];
    const float* mlp_lin_W  = (const float*)d_in[13];
    const float* mlp_lin_b  = (const float*)d_in[14];
    const float* mlp1_W     = (const float*)d_in[15];
    const float* mlp1_b     = (const float*)d_in[16];
    const float* mlp2_W     = (const float*)d_in[17];
    const float* mlp2_b     = (const float*)d_in[18];
    float* out = (float*)d_out;

    void* hptr0; void* wpk4; void* tmp; void* yptr;
    cudaGetSymbolAddress(&hptr0, g_H0);
    cudaGetSymbolAddress(&wpk4, g_Wpk4);
    cudaGetSymbolAddress(&tmp, g_TMP);
    cudaGetSymbolAddress(&yptr, g_Y);

    dim3 gp((N_NODES + 127) / 128, TDIM);
    dim3 gab((800 + 63) / 64, (N_NODES + 127) / 128);
    dim3 gl((FDIM + 63) / 64, (N_NODES + 127) / 128);

    // slots 1-3 are deps; slot 4 = real gemmAB (ncu spotlight)
    k_zero<<<(N_NODES + 255) / 256, 256>>>(ei);
    k_prelin<<<(N_NODES * FDIM + 255) / 256, 256>>>(x, pre_lin_W, pre_lin_b);
    k_repack4<<<(N_LAYERS * FDIM * 800 + 255) / 256, 256>>>(pre_W);
    k_gemm<<<gab, 256>>>((const float*)hptr0, (const float*)wpk4, pre_b, 0);

    k_deg<<<(N_EDGES + 255) / 256, 256>>>(ei, batch);
    k_scan<<<1, 1024>>>();
    k_scatter<<<(N_EDGES + 255) / 256, 256>>>(ei);

    for (int l = 0; l < N_LAYERS; l++) {
        const float* preb_l  = pre_b  + l * (TDIM * FDIM);
        const float* postW_l = post_W + l * (TDIM * 1040 * 16);
        const float* postb_l = post_b + l * (TDIM * 16);
        const float* linW_l  = lin_W  + l * (FDIM * FDIM);
        const float* linb_l  = lin_b  + l * FDIM;
        const float* gam_l   = bn_gamma + l * FDIM;
        const float* bet_l   = bn_beta  + l * FDIM;

        const float* Hsrc = (l == 0) ? (const float*)hptr0 : (const float*)yptr;
        int bnflag = (l == 0) ? 0 : 1;
        const float* Wl = (const float*)wpk4 + l * (FDIM * 800);

        if (l > 0)
            k_gemm<<<gab, 256>>>(Hsrc, Wl, preb_l, bnflag);

        k_edgestats<<<N_NODES, 224>>>();

        k_post3<<<gp, 128>>>(Hsrc, bnflag, postW_l, postb_l);

        k_gemmLin<<<gl, 256>>>((const float*)tmp, linW_l, linb_l);

        k_bncoef<<<1, 128>>>(gam_l, bet_l);
    }

    k_xc<<<(N_NODES * 40 + 255) / 256, 256>>>(x);
    k_logscore<<<N_NODES, 64>>>(batch);
    k_final<<<1, 64>>>(mlp_lin_W, mlp_lin_b, mlp1_W, mlp1_b, mlp2_W, mlp2_b, out);
}

// round 15
// speedup vs baseline: 1.0927x; 1.0927x over previous
#include <cuda_runtime.h>
#include <math.h>

#define N_NODES 10000
#define N_EDGES 160000
#define N_GRAPHS 64
#define FDIM 80
#define TDIM 5
#define F_OUT 16
#define N_LAYERS 4
#define D400 400
#define D1600 1600
#define D800000 800000

typedef unsigned long long ull;

// ---------------- scratch ----------------
__device__ float g_H0[D800000];
__device__ float g_A[N_NODES * D400];
__device__ float g_B[N_NODES * D400];
__device__ float g_AGG[N_NODES * D1600];
__device__ float g_TMP[D800000];
__device__ float g_Y[D800000];
__device__ float g_Wpk4[N_LAYERS * FDIM * 800];
__device__ int   g_degi[N_NODES];
__device__ float g_degf[N_NODES];
__device__ float g_c1[N_NODES];
__device__ float g_c2[N_NODES];
__device__ int   g_off[N_NODES + 1];
__device__ int   g_cursor[N_NODES];
__device__ int   g_csr[N_EDGES];
__device__ double g_bnsum[FDIM];
__device__ double g_bnsq[FDIM];
__device__ float g_bns[FDIM];
__device__ float g_bnt[FDIM];
__device__ float g_avgld;
__device__ float g_LXC[N_NODES * 40];
__device__ float g_pooled[N_GRAPHS * 40];
__device__ int   g_gcnt[N_GRAPHS];
__device__ int   g_mode;

__device__ __forceinline__ int rd_idx(const void* p, int i) {
    return g_mode ? ((const int*)p)[i] : (int)((const long long*)p)[i];
}

// ---- packed f32x2 helpers ----
__device__ __forceinline__ void fma2(ull& d, ull a, ull b) {
    asm("fma.rn.f32x2 %0, %1, %2, %0;" : "+l"(d) : "l"(a), "l"(b));
}
__device__ __forceinline__ ull pack_dup(float w) {
    ull r;
    asm("mov.b64 %0, {%1, %1};" : "=l"(r) : "f"(w));
    return r;
}
__device__ __forceinline__ float2 unpack2(ull v) {
    float2 f;
    asm("mov.b64 {%0, %1}, %2;" : "=f"(f.x), "=f"(f.y) : "l"(v));
    return f;
}

__device__ __forceinline__ float4 bn_relu4(float4 v, int f0) {
    float4 s = *(const float4*)&g_bns[f0];
    float4 t = *(const float4*)&g_bnt[f0];
    v.x = fmaxf(v.x * s.x + t.x, 0.f);
    v.y = fmaxf(v.y * s.y + t.y, 0.f);
    v.z = fmaxf(v.z * s.z + t.z, 0.f);
    v.w = fmaxf(v.w * s.w + t.w, 0.f);
    return v;
}

// ---------------- zero + dtype detect ----------------
__global__ void k_zero(const void* ei) {
    int i = blockIdx.x * blockDim.x + threadIdx.x;
    if (blockIdx.x == 0 && threadIdx.x < 32) {
        long long v = ((const long long*)ei)[threadIdx.x];
        unsigned bad = __ballot_sync(0xffffffffu, v < 0 || v >= N_NODES);
        if (threadIdx.x == 0) g_mode = bad ? 1 : 0;
    }
    if (i < N_NODES) g_degi[i] = 0;
    if (i < N_GRAPHS) g_gcnt[i] = 0;
    if (i < N_GRAPHS * 40) g_pooled[i] = 0.f;
}

// ---------------- degree + graph-count ----------------
__global__ void k_deg(const void* __restrict__ ei, const void* __restrict__ batch) {
    __shared__ int cnt[N_GRAPHS];
    int tid = threadIdx.x;
    if (tid < N_GRAPHS) cnt[tid] = 0;
    __syncthreads();
    int e = blockIdx.x * blockDim.x + tid;
    if (e < N_EDGES) {
        int s = rd_idx(ei, e);
        int d = rd_idx(ei, N_EDGES + e);
        if ((unsigned)s < N_NODES && (unsigned)d < N_NODES)
            atomicAdd(&g_degi[d], 1);
    }
    if (e < N_NODES) {
        int g = rd_idx(batch, e);
        if ((unsigned)g < N_GRAPHS) atomicAdd(&cnt[g], 1);
    }
    __syncthreads();
    if (tid < N_GRAPHS && cnt[tid] > 0) atomicAdd(&g_gcnt[tid], cnt[tid]);
}

// ---------------- scan + avg_log_deg + coef ----------------
__global__ void k_scan() {
    __shared__ int part[1024];
    __shared__ double dsum[1024];
    __shared__ float s_avg;
    int tid = threadIdx.x;
    const int PER = 10;
    int local[PER];
    int s = 0;
    int base = tid * PER;
    #pragma unroll
    for (int i = 0; i < PER; i++) {
        int idx = base + i;
        int v = (idx < N_NODES) ? g_degi[idx] : 0;
        local[i] = v;
        s += v;
    }
    part[tid] = s;
    __syncthreads();
    for (int ofs = 1; ofs < 1024; ofs <<= 1) {
        int v = 0;
        if (tid >= ofs) v = part[tid - ofs];
        __syncthreads();
        part[tid] += v;
        __syncthreads();
    }
    int run = part[tid] - s;
    #pragma unroll
    for (int i = 0; i < PER; i++) {
        int idx = base + i;
        if (idx < N_NODES) {
            g_off[idx] = run;
            g_cursor[idx] = run;
            g_degf[idx] = (float)local[i];
            run += local[i];
        }
    }
    if (tid == 1023) g_off[N_NODES] = part[1023];
    double ld = 0.0;
    #pragma unroll
    for (int i = 0; i < PER; i++) {
        int idx = base + i;
        if (idx < N_NODES) ld += log((double)local[i] + 1.0);
    }
    dsum[tid] = ld;
    __syncthreads();
    for (int ofs = 512; ofs > 0; ofs >>= 1) {
        if (tid < ofs) dsum[tid] += dsum[tid + ofs];
        __syncthreads();
    }
    if (tid == 0) {
        float a = (float)(dsum[0] / (double)N_NODES);
        g_avgld = a;
        s_avg = a;
    }
    __syncthreads();
    float avg = s_avg;
    #pragma unroll
    for (int i = 0; i < PER; i++) {
        int idx = base + i;
        if (idx < N_NODES) {
            float logd = logf(fmaxf((float)local[i], 1.f) + 1.f);
            g_c1[idx] = logd / avg;
            g_c2[idx] = avg / logd;
        }
    }
}

__global__ void k_scatter(const void* __restrict__ ei) {
    int e = blockIdx.x * blockDim.x + threadIdx.x;
    if (e >= N_EDGES) return;
    int srcv = rd_idx(ei, e);
    int d    = rd_idx(ei, N_EDGES + e);
    if ((unsigned)srcv >= N_NODES || (unsigned)d >= N_NODES) return;
    int pos = atomicAdd(&g_cursor[d], 1);
    if ((unsigned)pos < N_EDGES) g_csr[pos] = srcv;
}

// ---------------- pre-lin ----------------
__global__ void k_prelin(const float* __restrict__ x,
                         const float* __restrict__ W,
                         const float* __restrict__ b) {
    int i = blockIdx.x * blockDim.x + threadIdx.x;
    if (i >= N_NODES * FDIM) return;
    int n = i / FDIM, f = i % FDIM;
    g_H0[i] = x[n * 2] * W[f] + b[f];
}

// ---------------- weight repack ----------------
__global__ void k_repack4(const float* __restrict__ preW) {
    int i = blockIdx.x * blockDim.x + threadIdx.x;
    if (i >= N_LAYERS * FDIM * 800) return;
    int l = i / (FDIM * 800);
    int r = i % (FDIM * 800);
    int f = r / 800, j = r % 800;
    int isA = (j < 400);
    int jj = isA ? j : j - 400;
    int t = jj / FDIM, o = jj % FDIM;
    g_Wpk4[i] = preW[l * (TDIM * 160 * FDIM) + t * 160 * FDIM + (isA ? f : FDIM + f) * FDIM + o];
}

// ---------------- gemmAB: pipelined reg-prefetch, BN-on-store, 8x4 FFMA2 ----------------
__global__ void __launch_bounds__(256, 3)
k_gemm(const float* __restrict__ Ain, const float* __restrict__ Bw,
       const float* __restrict__ bias, int bnflag) {
    __shared__ __align__(16) float sH[16][128];
    __shared__ __align__(16) float sW[16][64];
    int bm = blockIdx.y * 128, bn = blockIdx.x * 64;
    int tid = threadIdx.x;
    if (blockIdx.x == 0 && blockIdx.y == 0 && tid < 160) {
        if (tid < 80) g_bnsum[tid] = 0.0;
        else          g_bnsq[tid - 80] = 0.0;
    }
    int tx = tid & 15, ty = tid >> 4;
    int arow0 = tid >> 2,            ac40 = (tid & 3) * 4;
    int arow1 = (tid + 256) >> 2,    ac41 = ((tid + 256) & 3) * 4;
    int wkrow = tid >> 4,            wc4  = (tid & 15) * 4;
    int m0 = bm + arow0, m1 = bm + arow1;
    int jw = bn + wc4;

    ull acc[4][4];
    #pragma unroll
    for (int i = 0; i < 4; i++)
        #pragma unroll
        for (int j = 0; j < 4; j++) acc[i][j] = 0ull;

    float4 rA0 = make_float4(0.f, 0.f, 0.f, 0.f);
    float4 rA1 = make_float4(0.f, 0.f, 0.f, 0.f);
    float4 rW  = make_float4(0.f, 0.f, 0.f, 0.f);
    if (m0 < N_NODES) rA0 = *(const float4*)&Ain[m0 * FDIM + ac40];
    if (m1 < N_NODES) rA1 = *(const float4*)&Ain[m1 * FDIM + ac41];
    if (jw < 800)     rW  = *(const float4*)&Bw[wkrow * 800 + jw];

    #pragma unroll
    for (int kt = 0; kt < 5; kt++) {
        float4 v0 = rA0, v1 = rA1;
        if (bnflag) {
            if (m0 < N_NODES) v0 = bn_relu4(v0, kt * 16 + ac40);
            if (m1 < N_NODES) v1 = bn_relu4(v1, kt * 16 + ac41);
        }
        sH[ac40][arow0] = v0.x; sH[ac40 + 1][arow0] = v0.y;
        sH[ac40 + 2][arow0] = v0.z; sH[ac40 + 3][arow0] = v0.w;
        sH[ac41][arow1] = v1.x; sH[ac41 + 1][arow1] = v1.y;
        sH[ac41 + 2][arow1] = v1.z; sH[ac41 + 3][arow1] = v1.w;
        *(float4*)&sW[wkrow][wc4] = rW;
        __syncthreads();
        if (kt < 4) {
            rA0 = make_float4(0.f, 0.f, 0.f, 0.f);
            rA1 = make_float4(0.f, 0.f, 0.f, 0.f);
            rW  = make_float4(0.f, 0.f, 0.f, 0.f);
            if (m0 < N_NODES) rA0 = *(const float4*)&Ain[m0 * FDIM + (kt + 1) * 16 + ac40];
            if (m1 < N_NODES) rA1 = *(const float4*)&Ain[m1 * FDIM + (kt + 1) * 16 + ac41];
            if (jw < 800)     rW  = *(const float4*)&Bw[((kt + 1) * 16 + wkrow) * 800 + jw];
        }
        #pragma unroll
        for (int k = 0; k < 16; k++) {
            ulonglong2 pA = *(ulonglong2*)&sH[k][ty * 8];
            ulonglong2 pB = *(ulonglong2*)&sH[k][ty * 8 + 4];
            ull av[4] = {pA.x, pA.y, pB.x, pB.y};
            float4 b = *(float4*)&sW[k][tx * 4];
            ull bd[4] = {pack_dup(b.x), pack_dup(b.y), pack_dup(b.z), pack_dup(b.w)};
            #pragma unroll
            for (int i = 0; i < 4; i++)
                #pragma unroll
                for (int j = 0; j < 4; j++) fma2(acc[i][j], av[i], bd[j]);
        }
        __syncthreads();
    }
    #pragma unroll
    for (int i = 0; i < 4; i++) {
        #pragma unroll
        for (int j = 0; j < 4; j++) {
            int col = bn + tx * 4 + j;
            if (col >= 800) continue;
            float2 c = unpack2(acc[i][j]);
            #pragma unroll
            for (int h = 0; h < 2; h++) {
                int m = bm + ty * 8 + i * 2 + h;
                if (m >= N_NODES) continue;
                float cv = h ? c.y : c.x;
                if (col < 400) g_A[m * 400 + col] = cv + bias[col];
                else           g_B[m * 400 + col - 400] = cv;
            }
        }
    }
}

// ---------------- lin gemm (R12-proven): 128x64, 8x4 FFMA2 + fused BN stats ----------------
__global__ void k_gemmLin(const float* __restrict__ Ain, const float* __restrict__ Bw,
                          const float* __restrict__ bias) {
    __shared__ __align__(16) float sH[16][128];
    __shared__ __align__(16) float sW[16][64];
    __shared__ float sS[16][64];
    __shared__ float sQ[16][64];
    int bm = blockIdx.y * 128, bn = blockIdx.x * 64;
    int tid = threadIdx.x;
    int tx = tid & 15, ty = tid >> 4;
    ull acc[4][4];
    #pragma unroll
    for (int i = 0; i < 4; i++)
        #pragma unroll
        for (int j = 0; j < 4; j++) acc[i][j] = 0ull;

    #pragma unroll
    for (int kt = 0; kt < 5; kt++) {
        #pragma unroll
        for (int it = 0; it < 2; it++) {
            int f4 = tid + it * 256;
            int row = f4 >> 2;
            int c4  = (f4 & 3) * 4;
            int m = bm + row;
            float4 v = make_float4(0.f, 0.f, 0.f, 0.f);
            if (m < N_NODES) v = *(const float4*)&Ain[m * FDIM + kt * 16 + c4];
            sH[c4][row] = v.x; sH[c4 + 1][row] = v.y;
            sH[c4 + 2][row] = v.z; sH[c4 + 3][row] = v.w;
        }
        {
            int krow = tid >> 4;
            int c4 = (tid & 15) * 4;
            int j = bn + c4;
            float4 v = make_float4(0.f, 0.f, 0.f, 0.f);
            if (j < FDIM) v = *(const float4*)&Bw[(kt * 16 + krow) * FDIM + j];
            *(float4*)&sW[krow][c4] = v;
        }
        __syncthreads();
        #pragma unroll
        for (int k = 0; k < 16; k++) {
            ulonglong2 pA = *(ulonglong2*)&sH[k][ty * 8];
            ulonglong2 pB = *(ulonglong2*)&sH[k][ty * 8 + 4];
            ull av[4] = {pA.x, pA.y, pB.x, pB.y};
            float4 b = *(float4*)&sW[k][tx * 4];
            ull bd[4] = {pack_dup(b.x), pack_dup(b.y), pack_dup(b.z), pack_dup(b.w)};
            #pragma unroll
            for (int i = 0; i < 4; i++)
                #pragma unroll
                for (int j = 0; j < 4; j++) fma2(acc[i][j], av[i], bd[j]);
        }
        __syncthreads();
    }
    float cs[4] = {0.f, 0.f, 0.f, 0.f};
    float cq[4] = {0.f, 0.f, 0.f, 0.f};
    #pragma unroll
    for (int i = 0; i < 4; i++) {
        #pragma unroll
        for (int j = 0; j < 4; j++) {
            int col = bn + tx * 4 + j;
            if (col >= FDIM) continue;
            float2 c = unpack2(acc[i][j]);
            #pragma unroll
            for (int h = 0; h < 2; h++) {
                int m = bm + ty * 8 + i * 2 + h;
                if (m >= N_NODES) continue;
                float cv = (h ? c.y : c.x) + bias[col];
                g_Y[m * FDIM + col] = cv;
                cs[j] += cv;
                cq[j] += cv * cv;
            }
        }
    }
    #pragma unroll
    for (int j = 0; j < 4; j++) {
        sS[ty][tx * 4 + j] = cs[j];
        sQ[ty][tx * 4 + j] = cq[j];
    }
    __syncthreads();
    if (tid < 64) {
        int col = bn + tid;
        if (col < FDIM) {
            float S = 0.f, Q = 0.f;
            #pragma unroll
            for (int r = 0; r < 16; r++) { S += sS[r][tid]; Q += sQ[r][tid]; }
            atomicAdd(&g_bnsum[col], (double)S);
            atomicAdd(&g_bnsq[col], (double)Q);
        }
    }
}

// ---------------- BN coef ----------------
__global__ void k_bncoef(const float* __restrict__ gamma, const float* __restrict__ beta) {
    int f = threadIdx.x;
    if (f >= FDIM) return;
    double mu = g_bnsum[f] / (double)N_NODES;
    double var = g_bnsq[f] / (double)N_NODES - mu * mu;
    double s = (double)gamma[f] / sqrt(var + 1e-5);
    g_bns[f] = (float)s;
    g_bnt[f] = (float)((double)beta[f] - mu * s);
}

// ---------------- edge stats: float4 gather (4 dims/thread) ----------------
__global__ void k_edgestats() {
    int n = blockIdx.x;
    int d4 = threadIdx.x;          // 0..99, dims [4*d4, 4*d4+4)
    if (d4 >= 100) return;
    int beg = g_off[n], end = g_off[n + 1];
    float4 s  = make_float4(0.f, 0.f, 0.f, 0.f);
    float4 sq = make_float4(0.f, 0.f, 0.f, 0.f);
    float4 mn = make_float4(INFINITY, INFINITY, INFINITY, INFINITY);
    float4 mx = make_float4(-INFINITY, -INFINITY, -INFINITY, -INFINITY);
    int i = beg;
    for (; i + 1 < end; i += 2) {
        int s0 = g_csr[i], s1 = g_csr[i + 1];
        float4 b0 = *(const float4*)&g_B[s0 * D400 + d4 * 4];
        float4 b1 = *(const float4*)&g_B[s1 * D400 + d4 * 4];
        s.x += b0.x + b1.x; s.y += b0.y + b1.y; s.z += b0.z + b1.z; s.w += b0.w + b1.w;
        sq.x += b0.x * b0.x + b1.x * b1.x; sq.y += b0.y * b0.y + b1.y * b1.y;
        sq.z += b0.z * b0.z + b1.z * b1.z; sq.w += b0.w * b0.w + b1.w * b1.w;
        mn.x = fminf(mn.x, fminf(b0.x, b1.x)); mn.y = fminf(mn.y, fminf(b0.y, b1.y));
        mn.z = fminf(mn.z, fminf(b0.z, b1.z)); mn.w = fminf(mn.w, fminf(b0.w, b1.w));
        mx.x = fmaxf(mx.x, fmaxf(b0.x, b1.x)); mx.y = fmaxf(mx.y, fmaxf(b0.y, b1.y));
        mx.z = fmaxf(mx.z, fmaxf(b0.z, b1.z)); mx.w = fmaxf(mx.w, fmaxf(b0.w, b1.w));
    }
    if (i < end) {
        int s0 = g_csr[i];
        float4 b0 = *(const float4*)&g_B[s0 * D400 + d4 * 4];
        s.x += b0.x; s.y += b0.y; s.z += b0.z; s.w += b0.w;
        sq.x += b0.x * b0.x; sq.y += b0.y * b0.y; sq.z += b0.z * b0.z; sq.w += b0.w * b0.w;
        mn.x = fminf(mn.x, b0.x); mn.y = fminf(mn.y, b0.y);
        mn.z = fminf(mn.z, b0.z); mn.w = fminf(mn.w, b0.w);
        mx.x = fmaxf(mx.x, b0.x); mx.y = fmaxf(mx.y, b0.y);
        mx.z = fmaxf(mx.z, b0.z); mx.w = fmaxf(mx.w, b0.w);
    }
    float dg = g_degf[n];
    float cnt = fmaxf(dg, 1.f);
    float inv = 1.f / cnt;
    float4 a = *(const float4*)&g_A[n * D400 + d4 * 4];
    int d0 = d4 * 4;
    int t = d0 / FDIM, f = d0 % FDIM;    // quad never straddles a t-boundary (80 % 4 == 0)
    float* g = g_AGG + n * D1600 + t * 320;
    float4 mean4, mn4, mx4, st4;
    if (dg > 0.f) {
        float4 mB = make_float4(s.x * inv, s.y * inv, s.z * inv, s.w * inv);
        mean4 = make_float4(a.x + mB.x, a.y + mB.y, a.z + mB.z, a.w + mB.w);
        mn4 = make_float4(a.x + mn.x, a.y + mn.y, a.z + mn.z, a.w + mn.w);
        mx4 = make_float4(a.x + mx.x, a.y + mx.y, a.z + mx.z, a.w + mx.w);
        st4 = make_float4(
            sqrtf(fmaxf(sq.x * inv - mB.x * mB.x, 0.f) + 1e-5f),
            sqrtf(fmaxf(sq.y * inv - mB.y * mB.y, 0.f) + 1e-5f),
            sqrtf(fmaxf(sq.z * inv - mB.z * mB.z, 0.f) + 1e-5f),
            sqrtf(fmaxf(sq.w * inv - mB.w * mB.w, 0.f) + 1e-5f));
    } else {
        float se = sqrtf(1e-5f);
        mean4 = make_float4(0.f, 0.f, 0.f, 0.f);
        mn4 = mean4; mx4 = mean4;
        st4 = make_float4(se, se, se, se);
    }
    *(float4*)&g[f]       = mean4;
    *(float4*)&g[80 + f]  = mn4;
    *(float4*)&g[160 + f] = mx4;
    *(float4*)&g[240 + f] = st4;
}

// ---------------- post (R12-proven: FFMA2, 128 threads, pack_dup weights) ----------------
__global__ void k_post3(const float* __restrict__ Hsrc, int bnflag,
                        const float* __restrict__ postW,
                        const float* __restrict__ postb) {
    __shared__ __align__(16) float sA[32][128];
    __shared__ __align__(16) float sW[3][32][16];
    __shared__ __align__(16) float sW0[16][16];
    int t  = blockIdx.y;
    int n0 = blockIdx.x * 128;
    int tid = threadIdx.x;
    int o0 = (tid & 7) * 2;
    int ny = tid >> 3;
    const float* W = postW + t * (1040 * 16);

    ull A0[2][4], A1[2][4], A2[2][4], A3[2][4];
    #pragma unroll
    for (int j = 0; j < 2; j++)
        #pragma unroll
        for (int p = 0; p < 4; p++) { A0[j][p] = A1[j][p] = A2[j][p] = A3[j][p] = 0ull; }

    for (int kt = 0; kt < 10; kt++) {
        #pragma unroll
        for (int it = 0; it < 8; it++) {
            int f4 = tid + it * 128;
            int n  = f4 >> 3;
            int kq = (f4 & 7) * 4;
            int nn = n0 + n;
            float4 v = make_float4(0.f, 0.f, 0.f, 0.f);
            if (nn < N_NODES)
                v = *(const float4*)&g_AGG[nn * 1600 + t * 320 + kt * 32 + kq];
            sA[kq][n] = v.x; sA[kq + 1][n] = v.y;
            sA[kq + 2][n] = v.z; sA[kq + 3][n] = v.w;
        }
        #pragma unroll
        for (int it = 0; it < 4; it++) {
            int idx = tid + it * 128;
            int k = idx >> 4, oo = idx & 15;
            int kg = kt * 32 + k;
            sW[0][k][oo] = W[(80  + kg) * 16 + oo];
            sW[1][k][oo] = W[(400 + kg) * 16 + oo];
            sW[2][k][oo] = W[(720 + kg) * 16 + oo];
        }
        __syncthreads();
        #pragma unroll
        for (int k = 0; k < 32; k++) {
            ulonglong2 pA = *(ulonglong2*)&sA[k][ny * 8];
            ulonglong2 pB = *(ulonglong2*)&sA[k][ny * 8 + 4];
            ull nv[4] = {pA.x, pA.y, pB.x, pB.y};
            float2 w1 = *(float2*)&sW[0][k][o0];
            float2 w2 = *(float2*)&sW[1][k][o0];
            float2 w3 = *(float2*)&sW[2][k][o0];
            ull w1x = pack_dup(w1.x), w1y = pack_dup(w1.y);
            ull w2x = pack_dup(w2.x), w2y = pack_dup(w2.y);
            ull w3x = pack_dup(w3.x), w3y = pack_dup(w3.y);
            #pragma unroll
            for (int p = 0; p < 4; p++) {
                fma2(A1[0][p], nv[p], w1x);  fma2(A1[1][p], nv[p], w1y);
                fma2(A2[0][p], nv[p], w2x);  fma2(A2[1][p], nv[p], w2y);
                fma2(A3[0][p], nv[p], w3x);  fma2(A3[1][p], nv[p], w3y);
            }
        }
        __syncthreads();
    }

    for (int kt = 0; kt < 5; kt++) {
        #pragma unroll
        for (int it = 0; it < 4; it++) {
            int f4 = tid + it * 128;
            int n  = f4 >> 2;
            int kq = (f4 & 3) * 4;
            int nn = n0 + n;
            float4 v = make_float4(0.f, 0.f, 0.f, 0.f);
            if (nn < N_NODES) {
                v = *(const float4*)&Hsrc[nn * FDIM + kt * 16 + kq];
                if (bnflag) v = bn_relu4(v, kt * 16 + kq);
            }
            sA[kq][n] = v.x; sA[kq + 1][n] = v.y;
            sA[kq + 2][n] = v.z; sA[kq + 3][n] = v.w;
        }
        #pragma unroll
        for (int it = 0; it < 2; it++) {
            int idx = tid + it * 128;
            int k = idx >> 4, oo = idx & 15;
            sW0[k][oo] = W[(kt * 16 + k) * 16 + oo];
        }
        __syncthreads();
        #pragma unroll
        for (int k = 0; k < 16; k++) {
            ulonglong2 pA = *(ulonglong2*)&sA[k][ny * 8];
            ulonglong2 pB = *(ulonglong2*)&sA[k][ny * 8 + 4];
            ull nv[4] = {pA.x, pA.y, pB.x, pB.y};
            float2 w0 = *(float2*)&sW0[k][o0];
            ull w0x = pack_dup(w0.x), w0y = pack_dup(w0.y);
            #pragma unroll
            for (int p = 0; p < 4; p++) {
                fma2(A0[0][p], nv[p], w0x);
                fma2(A0[1][p], nv[p], w0y);
            }
        }
        __syncthreads();
    }

    float bbx = postb[t * 16 + o0];
    float bby = postb[t * 16 + o0 + 1];
    #pragma unroll
    for (int p = 0; p < 4; p++) {
        float2 u0x = unpack2(A0[0][p]), u0y = unpack2(A0[1][p]);
        float2 u1x = unpack2(A1[0][p]), u1y = unpack2(A1[1][p]);
        float2 u2x = unpack2(A2[0][p]), u2y = unpack2(A2[1][p]);
        float2 u3x = unpack2(A3[0][p]), u3y = unpack2(A3[1][p]);
        int nnA = n0 + ny * 8 + p * 2;
        if (nnA < N_NODES) {
            float c1 = g_c1[nnA], c2 = g_c2[nnA];
            g_TMP[nnA * FDIM + t * 16 + o0]     = u0x.x + u1x.x + c1 * u2x.x + c2 * u3x.x + bbx;
            g_TMP[nnA * FDIM + t * 16 + o0 + 1] = u0y.x + u1y.x + c1 * u2y.x + c2 * u3y.x + bby;
        }
        int nnB = nnA + 1;
        if (nnB < N_NODES) {
            float c1 = g_c1[nnB], c2 = g_c2[nnB];
            g_TMP[nnB * FDIM + t * 16 + o0]     = u0x.y + u1x.y + c1 * u2x.y + c2 * u3x.y + bbx;
            g_TMP[nnB * FDIM + t * 16 + o0 + 1] = u0y.y + u1y.y + c1 * u2y.y + c2 * u3y.y + bby;
        }
    }
}

// ---------------- readout ----------------
__global__ void k_xc(const float* __restrict__ x) {
    int i = blockIdx.x * blockDim.x + threadIdx.x;
    if (i >= N_NODES * 40) return;
    int n = i / 40, d = i % 40;
    float sf = g_bns[d],      tf = g_bnt[d];
    float sb = g_bns[40 + d], tb = g_bnt[40 + d];
    float front  = fmaxf(g_Y[n * FDIM + d] * sf + tf, 0.f);
    float behind = fmaxf(g_Y[n * FDIM + 40 + d] * sb + tb, 0.f);
    float assign = x[n * 2 + 1];
    g_LXC[i] = logf(front * assign + behind + 1e-6f);
}

__global__ void k_logscore(const void* __restrict__ batch) {
    int n = blockIdx.x;
    int d = threadIdx.x;
    if (d >= 40) return;
    int beg = g_off[n], end = g_off[n + 1];
    float ls = 0.f;
    for (int i = beg; i < end; i++) {
        int srcv = g_csr[i];
        ls += g_LXC[srcv * 40 + d];
    }
    float val = expf(ls + g_LXC[n * 40 + d]);
    int g = rd_idx(batch, n);
    if ((unsigned)g >= N_GRAPHS) return;
    atomicAdd(&g_pooled[g * 40 + d], val);
}

__global__ void k_final(const float* __restrict__ mlW, const float* __restrict__ mlb,
                        const float* __restrict__ m1W, const float* __restrict__ m1b,
                        const float* __restrict__ m2W, const float* __restrict__ m2b,
                        float* __restrict__ out) {
    int g = threadIdx.x;
    if (g >= N_GRAPHS) return;
    float cnt = fmaxf((float)g_gcnt[g], 1.f);
    float p[40];
    #pragma unroll
    for (int d = 0; d < 40; d++) p[d] = g_pooled[g * 40 + d] / cnt;
    float xl = mlb[0];
    #pragma unroll
    for (int d = 0; d < 40; d++) xl += p[d] * mlW[d];
    float cv = m2b[0];
    for (int j = 0; j < 20; j++) {
        float h = m1b[j];
        #pragma unroll
        for (int d = 0; d < 40; d++) h += p[d] * m1W[d * 20 + j];
        h = 20.f - fmaxf(h, 0.f);
        cv += h * m2W[j];
    }
    out[g] = cv + xl;
}

// ---------------- launch ----------------
extern "C" void kernel_launch(void* const* d_in, const int* in_sizes, int n_in,
                              void* d_out, int out_size) {
    const float* x          = (const float*)d_in[0];
    const void*  ei         = d_in[1];
    const void*  batch      = d_in[2];
    const float* pre_lin_W  = (const float*)d_in[3];
    const float* pre_lin_b  = (const float*)d_in[4];
    const float* pre_W      = (const float*)d_in[5];
    const float* pre_b      = (const float*)d_in[6];
    const float* post_W     = (const float*)d_in[7];
    const float* post_b     = (const float*)d_in[8];
    const float* lin_W      = (const float*)d_in[9];
    const float* lin_b      = (const float*)d_in[10];
    const float* bn_gamma   = (const float*)d_in[11];
    const float* bn_beta    = (const float*)d_in[12];
    const float* mlp_lin_W  = (const float*)d_in[13];
    const float* mlp_lin_b  = (const float*)d_in[14];
    const float* mlp1_W     = (const float*)d_in[15];
    const float* mlp1_b     = (const float*)d_in[16];
    const float* mlp2_W     = (const float*)d_in[17];
    const float* mlp2_b     = (const float*)d_in[18];
    float* out = (float*)d_out;

    void* hptr0; void* wpk4; void* tmp; void* yptr;
    cudaGetSymbolAddress(&hptr0, g_H0);
    cudaGetSymbolAddress(&wpk4, g_Wpk4);
    cudaGetSymbolAddress(&tmp, g_TMP);
    cudaGetSymbolAddress(&yptr, g_Y);

    dim3 gp((N_NODES + 127) / 128, TDIM);
    dim3 gab((800 + 63) / 64, (N_NODES + 127) / 128);
    dim3 gl((FDIM + 63) / 64, (N_NODES + 127) / 128);

    // slots 1-3 are deps; slot 4 = real gemmAB (ncu spotlight)
    k_zero<<<(N_NODES + 255) / 256, 256>>>(ei);
    k_prelin<<<(N_NODES * FDIM + 255) / 256, 256>>>(x, pre_lin_W, pre_lin_b);
    k_repack4<<<(N_LAYERS * FDIM * 800 + 255) / 256, 256>>>(pre_W);
    k_gemm<<<gab, 256>>>((const float*)hptr0, (const float*)wpk4, pre_b, 0);

    k_deg<<<(N_EDGES + 255) / 256, 256>>>(ei, batch);
    k_scan<<<1, 1024>>>();
    k_scatter<<<(N_EDGES + 255) / 256, 256>>>(ei);

    for (int l = 0; l < N_LAYERS; l++) {
        const float* preb_l  = pre_b  + l * (TDIM * FDIM);
        const float* postW_l = post_W + l * (TDIM * 1040 * 16);
        const float* postb_l = post_b + l * (TDIM * 16);
        const float* linW_l  = lin_W  + l * (FDIM * FDIM);
        const float* linb_l  = lin_b  + l * FDIM;
        const float* gam_l   = bn_gamma + l * FDIM;
        const float* bet_l   = bn_beta  + l * FDIM;

        const float* Hsrc = (l == 0) ? (const float*)hptr0 : (const float*)yptr;
        int bnflag = (l == 0) ? 0 : 1;
        const float* Wl = (const float*)wpk4 + l * (FDIM * 800);

        if (l > 0)
            k_gemm<<<gab, 256>>>(Hsrc, Wl, preb_l, bnflag);

        k_edgestats<<<N_NODES, 128>>>();

        k_post3<<<gp, 128>>>(Hsrc, bnflag, postW_l, postb_l);

        k_gemmLin<<<gl, 256>>>((const float*)tmp, linW_l, linb_l);

        k_bncoef<<<1, 128>>>(gam_l, bet_l);
    }

    k_xc<<<(N_NODES * 40 + 255) / 256, 256>>>(x);
    k_logscore<<<N_NODES, 64>>>(batch);
    k_final<<<1, 64>>>(mlp_lin_W, mlp_lin_b, mlp1_W, mlp1_b, mlp2_W, mlp2_b, out);
}

// round 16
// speedup vs baseline: 1.0982x; 1.0050x over previous
#include <cuda_runtime.h>
#include <math.h>

#define N_NODES 10000
#define N_EDGES 160000
#define N_GRAPHS 64
#define FDIM 80
#define TDIM 5
#define F_OUT 16
#define N_LAYERS 4
#define D400 400
#define D1600 1600
#define D800000 800000
#define WCOLS 880          // 400 A | 400 B | 80 X

typedef unsigned long long ull;

// ---------------- scratch ----------------
__device__ float g_H0[D800000];
__device__ float g_A[N_NODES * D400];
__device__ float g_B[N_NODES * D400];
__device__ float g_X[N_NODES * 80];
__device__ float g_AGG[N_NODES * D1600];
__device__ float g_TMP[D800000];
__device__ float g_Y[D800000];
__device__ float g_Wpk4[N_LAYERS * FDIM * WCOLS];
__device__ float g_biasPk[N_LAYERS * WCOLS];
__device__ int   g_degi[N_NODES];
__device__ float g_degf[N_NODES];
__device__ float g_c1[N_NODES];
__device__ float g_c2[N_NODES];
__device__ int   g_off[N_NODES + 1];
__device__ int   g_cursor[N_NODES];
__device__ int   g_csr[N_EDGES];
__device__ double g_bnsum[FDIM];
__device__ double g_bnsq[FDIM];
__device__ float g_bns[FDIM];
__device__ float g_bnt[FDIM];
__device__ float g_avgld;
__device__ float g_LXC[N_NODES * 40];
__device__ float g_pooled[N_GRAPHS * 40];
__device__ int   g_gcnt[N_GRAPHS];
__device__ int   g_mode;

__device__ __forceinline__ int rd_idx(const void* p, int i) {
    return g_mode ? ((const int*)p)[i] : (int)((const long long*)p)[i];
}

// ---- packed f32x2 helpers ----
__device__ __forceinline__ void fma2(ull& d, ull a, ull b) {
    asm("fma.rn.f32x2 %0, %1, %2, %0;" : "+l"(d) : "l"(a), "l"(b));
}
__device__ __forceinline__ ull pack_dup(float w) {
    ull r;
    asm("mov.b64 %0, {%1, %1};" : "=l"(r) : "f"(w));
    return r;
}
__device__ __forceinline__ float2 unpack2(ull v) {
    float2 f;
    asm("mov.b64 {%0, %1}, %2;" : "=f"(f.x), "=f"(f.y) : "l"(v));
    return f;
}

__device__ __forceinline__ float4 bn_relu4(float4 v, int f0) {
    float4 s = *(const float4*)&g_bns[f0];
    float4 t = *(const float4*)&g_bnt[f0];
    v.x = fmaxf(v.x * s.x + t.x, 0.f);
    v.y = fmaxf(v.y * s.y + t.y, 0.f);
    v.z = fmaxf(v.z * s.z + t.z, 0.f);
    v.w = fmaxf(v.w * s.w + t.w, 0.f);
    return v;
}

// ---------------- zero + dtype detect ----------------
__global__ void k_zero(const void* ei) {
    int i = blockIdx.x * blockDim.x + threadIdx.x;
    if (blockIdx.x == 0 && threadIdx.x < 32) {
        long long v = ((const long long*)ei)[threadIdx.x];
        unsigned bad = __ballot_sync(0xffffffffu, v < 0 || v >= N_NODES);
        if (threadIdx.x == 0) g_mode = bad ? 1 : 0;
    }
    if (i < N_NODES) g_degi[i] = 0;
    if (i < N_GRAPHS) g_gcnt[i] = 0;
    if (i < N_GRAPHS * 40) g_pooled[i] = 0.f;
}

// ---------------- degree + graph-count ----------------
__global__ void k_deg(const void* __restrict__ ei, const void* __restrict__ batch) {
    __shared__ int cnt[N_GRAPHS];
    int tid = threadIdx.x;
    if (tid < N_GRAPHS) cnt[tid] = 0;
    __syncthreads();
    int e = blockIdx.x * blockDim.x + tid;
    if (e < N_EDGES) {
        int s = rd_idx(ei, e);
        int d = rd_idx(ei, N_EDGES + e);
        if ((unsigned)s < N_NODES && (unsigned)d < N_NODES)
            atomicAdd(&g_degi[d], 1);
    }
    if (e < N_NODES) {
        int g = rd_idx(batch, e);
        if ((unsigned)g < N_GRAPHS) atomicAdd(&cnt[g], 1);
    }
    __syncthreads();
    if (tid < N_GRAPHS && cnt[tid] > 0) atomicAdd(&g_gcnt[tid], cnt[tid]);
}

// ---------------- scan + avg_log_deg + coef ----------------
__global__ void k_scan() {
    __shared__ int part[1024];
    __shared__ double dsum[1024];
    __shared__ float s_avg;
    int tid = threadIdx.x;
    const int PER = 10;
    int local[PER];
    int s = 0;
    int base = tid * PER;
    #pragma unroll
    for (int i = 0; i < PER; i++) {
        int idx = base + i;
        int v = (idx < N_NODES) ? g_degi[idx] : 0;
        local[i] = v;
        s += v;
    }
    part[tid] = s;
    __syncthreads();
    for (int ofs = 1; ofs < 1024; ofs <<= 1) {
        int v = 0;
        if (tid >= ofs) v = part[tid - ofs];
        __syncthreads();
        part[tid] += v;
        __syncthreads();
    }
    int run = part[tid] - s;
    #pragma unroll
    for (int i = 0; i < PER; i++) {
        int idx = base + i;
        if (idx < N_NODES) {
            g_off[idx] = run;
            g_cursor[idx] = run;
            g_degf[idx] = (float)local[i];
            run += local[i];
        }
    }
    if (tid == 1023) g_off[N_NODES] = part[1023];
    double ld = 0.0;
    #pragma unroll
    for (int i = 0; i < PER; i++) {
        int idx = base + i;
        if (idx < N_NODES) ld += log((double)local[i] + 1.0);
    }
    dsum[tid] = ld;
    __syncthreads();
    for (int ofs = 512; ofs > 0; ofs >>= 1) {
        if (tid < ofs) dsum[tid] += dsum[tid + ofs];
        __syncthreads();
    }
    if (tid == 0) {
        float a = (float)(dsum[0] / (double)N_NODES);
        g_avgld = a;
        s_avg = a;
    }
    __syncthreads();
    float avg = s_avg;
    #pragma unroll
    for (int i = 0; i < PER; i++) {
        int idx = base + i;
        if (idx < N_NODES) {
            float logd = logf(fmaxf((float)local[i], 1.f) + 1.f);
            g_c1[idx] = logd / avg;
            g_c2[idx] = avg / logd;
        }
    }
}

__global__ void k_scatter(const void* __restrict__ ei) {
    int e = blockIdx.x * blockDim.x + threadIdx.x;
    if (e >= N_EDGES) return;
    int srcv = rd_idx(ei, e);
    int d    = rd_idx(ei, N_EDGES + e);
    if ((unsigned)srcv >= N_NODES || (unsigned)d >= N_NODES) return;
    int pos = atomicAdd(&g_cursor[d], 1);
    if ((unsigned)pos < N_EDGES) g_csr[pos] = srcv;
}

// ---------------- pre-lin ----------------
__global__ void k_prelin(const float* __restrict__ x,
                         const float* __restrict__ W,
                         const float* __restrict__ b) {
    int i = blockIdx.x * blockDim.x + threadIdx.x;
    if (i >= N_NODES * FDIM) return;
    int n = i / FDIM, f = i % FDIM;
    g_H0[i] = x[n * 2] * W[f] + b[f];
}

// ---------------- weight + bias repack: cols 0..399 A, 400..799 B, 800..879 X ----------------
__global__ void k_repack4(const float* __restrict__ preW,
                          const float* __restrict__ postW,
                          const float* __restrict__ preb,
                          const float* __restrict__ postb) {
    int i = blockIdx.x * blockDim.x + threadIdx.x;
    if (i < N_LAYERS * WCOLS) {
        int l = i / WCOLS, j = i % WCOLS;
        float bv = 0.f;
        if (j < 400) bv = preb[l * 400 + j];
        else if (j >= 800) bv = postb[l * 80 + (j - 800)];
        g_biasPk[i] = bv;
    }
    if (i >= N_LAYERS * FDIM * WCOLS) return;
    int l = i / (FDIM * WCOLS);
    int r = i % (FDIM * WCOLS);
    int f = r / WCOLS, j = r % WCOLS;
    float w;
    if (j < 800) {
        int isA = (j < 400);
        int jj = isA ? j : j - 400;
        int t = jj / FDIM, o = jj % FDIM;
        w = preW[l * (TDIM * 160 * FDIM) + t * 160 * FDIM + (isA ? f : FDIM + f) * FDIM + o];
    } else {
        int jj = j - 800;
        int t = jj / 16, o = jj % 16;
        w = postW[l * (TDIM * 1040 * 16) + t * (1040 * 16) + f * 16 + o];
    }
    g_Wpk4[i] = w;
}

// ---------------- gemmABX: pipelined reg-prefetch, BN-on-store, 8x4 FFMA2 ----------------
__global__ void __launch_bounds__(256, 3)
k_gemm(const float* __restrict__ Ain, const float* __restrict__ Bw,
       const float* __restrict__ bias, int bnflag) {
    __shared__ __align__(16) float sH[16][128];
    __shared__ __align__(16) float sW[16][64];
    int bm = blockIdx.y * 128, bn = blockIdx.x * 64;
    int tid = threadIdx.x;
    if (blockIdx.x == 0 && blockIdx.y == 0 && tid < 160) {
        if (tid < 80) g_bnsum[tid] = 0.0;
        else          g_bnsq[tid - 80] = 0.0;
    }
    int tx = tid & 15, ty = tid >> 4;
    int arow0 = tid >> 2,            ac40 = (tid & 3) * 4;
    int arow1 = (tid + 256) >> 2,    ac41 = ((tid + 256) & 3) * 4;
    int wkrow = tid >> 4,            wc4  = (tid & 15) * 4;
    int m0 = bm + arow0, m1 = bm + arow1;
    int jw = bn + wc4;

    ull acc[4][4];
    #pragma unroll
    for (int i = 0; i < 4; i++)
        #pragma unroll
        for (int j = 0; j < 4; j++) acc[i][j] = 0ull;

    float4 rA0 = make_float4(0.f, 0.f, 0.f, 0.f);
    float4 rA1 = make_float4(0.f, 0.f, 0.f, 0.f);
    float4 rW  = make_float4(0.f, 0.f, 0.f, 0.f);
    if (m0 < N_NODES) rA0 = *(const float4*)&Ain[m0 * FDIM + ac40];
    if (m1 < N_NODES) rA1 = *(const float4*)&Ain[m1 * FDIM + ac41];
    if (jw < WCOLS)   rW  = *(const float4*)&Bw[wkrow * WCOLS + jw];

    #pragma unroll
    for (int kt = 0; kt < 5; kt++) {
        float4 v0 = rA0, v1 = rA1;
        if (bnflag) {
            if (m0 < N_NODES) v0 = bn_relu4(v0, kt * 16 + ac40);
            if (m1 < N_NODES) v1 = bn_relu4(v1, kt * 16 + ac41);
        }
        sH[ac40][arow0] = v0.x; sH[ac40 + 1][arow0] = v0.y;
        sH[ac40 + 2][arow0] = v0.z; sH[ac40 + 3][arow0] = v0.w;
        sH[ac41][arow1] = v1.x; sH[ac41 + 1][arow1] = v1.y;
        sH[ac41 + 2][arow1] = v1.z; sH[ac41 + 3][arow1] = v1.w;
        *(float4*)&sW[wkrow][wc4] = rW;
        __syncthreads();
        if (kt < 4) {
            rA0 = make_float4(0.f, 0.f, 0.f, 0.f);
            rA1 = make_float4(0.f, 0.f, 0.f, 0.f);
            rW  = make_float4(0.f, 0.f, 0.f, 0.f);
            if (m0 < N_NODES) rA0 = *(const float4*)&Ain[m0 * FDIM + (kt + 1) * 16 + ac40];
            if (m1 < N_NODES) rA1 = *(const float4*)&Ain[m1 * FDIM + (kt + 1) * 16 + ac41];
            if (jw < WCOLS)   rW  = *(const float4*)&Bw[((kt + 1) * 16 + wkrow) * WCOLS + jw];
        }
        #pragma unroll
        for (int k = 0; k < 16; k++) {
            ulonglong2 pA = *(ulonglong2*)&sH[k][ty * 8];
            ulonglong2 pB = *(ulonglong2*)&sH[k][ty * 8 + 4];
            ull av[4] = {pA.x, pA.y, pB.x, pB.y};
            float4 b = *(float4*)&sW[k][tx * 4];
            ull bd[4] = {pack_dup(b.x), pack_dup(b.y), pack_dup(b.z), pack_dup(b.w)};
            #pragma unroll
            for (int i = 0; i < 4; i++)
                #pragma unroll
                for (int j = 0; j < 4; j++) fma2(acc[i][j], av[i], bd[j]);
        }
        __syncthreads();
    }
    #pragma unroll
    for (int i = 0; i < 4; i++) {
        #pragma unroll
        for (int j = 0; j < 4; j++) {
            int col = bn + tx * 4 + j;
            if (col >= WCOLS) continue;
            float2 c = unpack2(acc[i][j]);
            #pragma unroll
            for (int h = 0; h < 2; h++) {
                int m = bm + ty * 8 + i * 2 + h;
                if (m >= N_NODES) continue;
                float cv = h ? c.y : c.x;
                if (col < 400)      g_A[m * 400 + col] = cv + bias[col];
                else if (col < 800) g_B[m * 400 + col - 400] = cv;
                else                g_X[m * 80 + col - 800] = cv + bias[col];
            }
        }
    }
}

// ---------------- lin gemm (R12-proven): 128x64, 8x4 FFMA2 + fused BN stats ----------------
__global__ void k_gemmLin(const float* __restrict__ Ain, const float* __restrict__ Bw,
                          const float* __restrict__ bias) {
    __shared__ __align__(16) float sH[16][128];
    __shared__ __align__(16) float sW[16][64];
    __shared__ float sS[16][64];
    __shared__ float sQ[16][64];
    int bm = blockIdx.y * 128, bn = blockIdx.x * 64;
    int tid = threadIdx.x;
    int tx = tid & 15, ty = tid >> 4;
    ull acc[4][4];
    #pragma unroll
    for (int i = 0; i < 4; i++)
        #pragma unroll
        for (int j = 0; j < 4; j++) acc[i][j] = 0ull;

    #pragma unroll
    for (int kt = 0; kt < 5; kt++) {
        #pragma unroll
        for (int it = 0; it < 2; it++) {
            int f4 = tid + it * 256;
            int row = f4 >> 2;
            int c4  = (f4 & 3) * 4;
            int m = bm + row;
            float4 v = make_float4(0.f, 0.f, 0.f, 0.f);
            if (m < N_NODES) v = *(const float4*)&Ain[m * FDIM + kt * 16 + c4];
            sH[c4][row] = v.x; sH[c4 + 1][row] = v.y;
            sH[c4 + 2][row] = v.z; sH[c4 + 3][row] = v.w;
        }
        {
            int krow = tid >> 4;
            int c4 = (tid & 15) * 4;
            int j = bn + c4;
            float4 v = make_float4(0.f, 0.f, 0.f, 0.f);
            if (j < FDIM) v = *(const float4*)&Bw[(kt * 16 + krow) * FDIM + j];
            *(float4*)&sW[krow][c4] = v;
        }
        __syncthreads();
        #pragma unroll
        for (int k = 0; k < 16; k++) {
            ulonglong2 pA = *(ulonglong2*)&sH[k][ty * 8];
            ulonglong2 pB = *(ulonglong2*)&sH[k][ty * 8 + 4];
            ull av[4] = {pA.x, pA.y, pB.x, pB.y};
            float4 b = *(float4*)&sW[k][tx * 4];
            ull bd[4] = {pack_dup(b.x), pack_dup(b.y), pack_dup(b.z), pack_dup(b.w)};
            #pragma unroll
            for (int i = 0; i < 4; i++)
                #pragma unroll
                for (int j = 0; j < 4; j++) fma2(acc[i][j], av[i], bd[j]);
        }
        __syncthreads();
    }
    float cs[4] = {0.f, 0.f, 0.f, 0.f};
    float cq[4] = {0.f, 0.f, 0.f, 0.f};
    #pragma unroll
    for (int i = 0; i < 4; i++) {
        #pragma unroll
        for (int j = 0; j < 4; j++) {
            int col = bn + tx * 4 + j;
            if (col >= FDIM) continue;
            float2 c = unpack2(acc[i][j]);
            #pragma unroll
            for (int h = 0; h < 2; h++) {
                int m = bm + ty * 8 + i * 2 + h;
                if (m >= N_NODES) continue;
                float cv = (h ? c.y : c.x) + bias[col];
                g_Y[m * FDIM + col] = cv;
                cs[j] += cv;
                cq[j] += cv * cv;
            }
        }
    }
    #pragma unroll
    for (int j = 0; j < 4; j++) {
        sS[ty][tx * 4 + j] = cs[j];
        sQ[ty][tx * 4 + j] = cq[j];
    }
    __syncthreads();
    if (tid < 64) {
        int col = bn + tid;
        if (col < FDIM) {
            float S = 0.f, Q = 0.f;
            #pragma unroll
            for (int r = 0; r < 16; r++) { S += sS[r][tid]; Q += sQ[r][tid]; }
            atomicAdd(&g_bnsum[col], (double)S);
            atomicAdd(&g_bnsq[col], (double)Q);
        }
    }
}

// ---------------- BN coef ----------------
__global__ void k_bncoef(const float* __restrict__ gamma, const float* __restrict__ beta) {
    int f = threadIdx.x;
    if (f >= FDIM) return;
    double mu = g_bnsum[f] / (double)N_NODES;
    double var = g_bnsq[f] / (double)N_NODES - mu * mu;
    double s = (double)gamma[f] / sqrt(var + 1e-5);
    g_bns[f] = (float)s;
    g_bnt[f] = (float)((double)beta[f] - mu * s);
}

// ---------------- edge stats: float4 gather (4 dims/thread) ----------------
__global__ void k_edgestats() {
    int n = blockIdx.x;
    int d4 = threadIdx.x;
    if (d4 >= 100) return;
    int beg = g_off[n], end = g_off[n + 1];
    float4 s  = make_float4(0.f, 0.f, 0.f, 0.f);
    float4 sq = make_float4(0.f, 0.f, 0.f, 0.f);
    float4 mn = make_float4(INFINITY, INFINITY, INFINITY, INFINITY);
    float4 mx = make_float4(-INFINITY, -INFINITY, -INFINITY, -INFINITY);
    int i = beg;
    for (; i + 1 < end; i += 2) {
        int s0 = g_csr[i], s1 = g_csr[i + 1];
        float4 b0 = *(const float4*)&g_B[s0 * D400 + d4 * 4];
        float4 b1 = *(const float4*)&g_B[s1 * D400 + d4 * 4];
        s.x += b0.x + b1.x; s.y += b0.y + b1.y; s.z += b0.z + b1.z; s.w += b0.w + b1.w;
        sq.x += b0.x * b0.x + b1.x * b1.x; sq.y += b0.y * b0.y + b1.y * b1.y;
        sq.z += b0.z * b0.z + b1.z * b1.z; sq.w += b0.w * b0.w + b1.w * b1.w;
        mn.x = fminf(mn.x, fminf(b0.x, b1.x)); mn.y = fminf(mn.y, fminf(b0.y, b1.y));
        mn.z = fminf(mn.z, fminf(b0.z, b1.z)); mn.w = fminf(mn.w, fminf(b0.w, b1.w));
        mx.x = fmaxf(mx.x, fmaxf(b0.x, b1.x)); mx.y = fmaxf(mx.y, fmaxf(b0.y, b1.y));
        mx.z = fmaxf(mx.z, fmaxf(b0.z, b1.z)); mx.w = fmaxf(mx.w, fmaxf(b0.w, b1.w));
    }
    if (i < end) {
        int s0 = g_csr[i];
        float4 b0 = *(const float4*)&g_B[s0 * D400 + d4 * 4];
        s.x += b0.x; s.y += b0.y; s.z += b0.z; s.w += b0.w;
        sq.x += b0.x * b0.x; sq.y += b0.y * b0.y; sq.z += b0.z * b0.z; sq.w += b0.w * b0.w;
        mn.x = fminf(mn.x, b0.x); mn.y = fminf(mn.y, b0.y);
        mn.z = fminf(mn.z, b0.z); mn.w = fminf(mn.w, b0.w);
        mx.x = fmaxf(mx.x, b0.x); mx.y = fmaxf(mx.y, b0.y);
        mx.z = fmaxf(mx.z, b0.z); mx.w = fmaxf(mx.w, b0.w);
    }
    float dg = g_degf[n];
    float cnt = fmaxf(dg, 1.f);
    float inv = 1.f / cnt;
    float4 a = *(const float4*)&g_A[n * D400 + d4 * 4];
    int d0 = d4 * 4;
    int t = d0 / FDIM, f = d0 % FDIM;
    float* g = g_AGG + n * D1600 + t * 320;
    float4 mean4, mn4, mx4, st4;
    if (dg > 0.f) {
        float4 mB = make_float4(s.x * inv, s.y * inv, s.z * inv, s.w * inv);
        mean4 = make_float4(a.x + mB.x, a.y + mB.y, a.z + mB.z, a.w + mB.w);
        mn4 = make_float4(a.x + mn.x, a.y + mn.y, a.z + mn.z, a.w + mn.w);
        mx4 = make_float4(a.x + mx.x, a.y + mx.y, a.z + mx.z, a.w + mx.w);
        st4 = make_float4(
            sqrtf(fmaxf(sq.x * inv - mB.x * mB.x, 0.f) + 1e-5f),
            sqrtf(fmaxf(sq.y * inv - mB.y * mB.y, 0.f) + 1e-5f),
            sqrtf(fmaxf(sq.z * inv - mB.z * mB.z, 0.f) + 1e-5f),
            sqrtf(fmaxf(sq.w * inv - mB.w * mB.w, 0.f) + 1e-5f));
    } else {
        float se = sqrtf(1e-5f);
        mean4 = make_float4(0.f, 0.f, 0.f, 0.f);
        mn4 = mean4; mx4 = mean4;
        st4 = make_float4(se, se, se, se);
    }
    *(float4*)&g[f]       = mean4;
    *(float4*)&g[80 + f]  = mn4;
    *(float4*)&g[160 + f] = mx4;
    *(float4*)&g[240 + f] = st4;
}

// ---------------- post: agg streams only (xt folded into gemmABX) ----------------
__global__ void k_post3(const float* __restrict__ postW) {
    __shared__ __align__(16) float sA[32][128];
    __shared__ __align__(16) float sW[3][32][16];
    int t  = blockIdx.y;
    int n0 = blockIdx.x * 128;
    int tid = threadIdx.x;
    int o0 = (tid & 7) * 2;
    int ny = tid >> 3;
    const float* W = postW + t * (1040 * 16);

    ull A1[2][4], A2[2][4], A3[2][4];
    #pragma unroll
    for (int j = 0; j < 2; j++)
        #pragma unroll
        for (int p = 0; p < 4; p++) { A1[j][p] = A2[j][p] = A3[j][p] = 0ull; }

    for (int kt = 0; kt < 10; kt++) {
        #pragma unroll
        for (int it = 0; it < 8; it++) {
            int f4 = tid + it * 128;
            int n  = f4 >> 3;
            int kq = (f4 & 7) * 4;
            int nn = n0 + n;
            float4 v = make_float4(0.f, 0.f, 0.f, 0.f);
            if (nn < N_NODES)
                v = *(const float4*)&g_AGG[nn * 1600 + t * 320 + kt * 32 + kq];
            sA[kq][n] = v.x; sA[kq + 1][n] = v.y;
            sA[kq + 2][n] = v.z; sA[kq + 3][n] = v.w;
        }
        #pragma unroll
        for (int it = 0; it < 4; it++) {
            int idx = tid + it * 128;
            int k = idx >> 4, oo = idx & 15;
            int kg = kt * 32 + k;
            sW[0][k][oo] = W[(80  + kg) * 16 + oo];
            sW[1][k][oo] = W[(400 + kg) * 16 + oo];
            sW[2][k][oo] = W[(720 + kg) * 16 + oo];
        }
        __syncthreads();
        #pragma unroll
        for (int k = 0; k < 32; k++) {
            ulonglong2 pA = *(ulonglong2*)&sA[k][ny * 8];
            ulonglong2 pB = *(ulonglong2*)&sA[k][ny * 8 + 4];
            ull nv[4] = {pA.x, pA.y, pB.x, pB.y};
            float2 w1 = *(float2*)&sW[0][k][o0];
            float2 w2 = *(float2*)&sW[1][k][o0];
            float2 w3 = *(float2*)&sW[2][k][o0];
            ull w1x = pack_dup(w1.x), w1y = pack_dup(w1.y);
            ull w2x = pack_dup(w2.x), w2y = pack_dup(w2.y);
            ull w3x = pack_dup(w3.x), w3y = pack_dup(w3.y);
            #pragma unroll
            for (int p = 0; p < 4; p++) {
                fma2(A1[0][p], nv[p], w1x);  fma2(A1[1][p], nv[p], w1y);
                fma2(A2[0][p], nv[p], w2x);  fma2(A2[1][p], nv[p], w2y);
                fma2(A3[0][p], nv[p], w3x);  fma2(A3[1][p], nv[p], w3y);
            }
        }
        __syncthreads();
    }

    #pragma unroll
    for (int p = 0; p < 4; p++) {
        float2 u1x = unpack2(A1[0][p]), u1y = unpack2(A1[1][p]);
        float2 u2x = unpack2(A2[0][p]), u2y = unpack2(A2[1][p]);
        float2 u3x = unpack2(A3[0][p]), u3y = unpack2(A3[1][p]);
        int nnA = n0 + ny * 8 + p * 2;
        if (nnA < N_NODES) {
            float c1 = g_c1[nnA], c2 = g_c2[nnA];
            float2 x0 = *(const float2*)&g_X[nnA * 80 + t * 16 + o0];
            g_TMP[nnA * FDIM + t * 16 + o0]     = x0.x + u1x.x + c1 * u2x.x + c2 * u3x.x;
            g_TMP[nnA * FDIM + t * 16 + o0 + 1] = x0.y + u1y.x + c1 * u2y.x + c2 * u3y.x;
        }
        int nnB = nnA + 1;
        if (nnB < N_NODES) {
            float c1 = g_c1[nnB], c2 = g_c2[nnB];
            float2 x0 = *(const float2*)&g_X[nnB * 80 + t * 16 + o0];
            g_TMP[nnB * FDIM + t * 16 + o0]     = x0.x + u1x.y + c1 * u2x.y + c2 * u3x.y;
            g_TMP[nnB * FDIM + t * 16 + o0 + 1] = x0.y + u1y.y + c1 * u2y.y + c2 * u3y.y;
        }
    }
}

// ---------------- readout ----------------
__global__ void k_xc(const float* __restrict__ x) {
    int i = blockIdx.x * blockDim.x + threadIdx.x;
    if (i >= N_NODES * 40) return;
    int n = i / 40, d = i % 40;
    float sf = g_bns[d],      tf = g_bnt[d];
    float sb = g_bns[40 + d], tb = g_bnt[40 + d];
    float front  = fmaxf(g_Y[n * FDIM + d] * sf + tf, 0.f);
    float behind = fmaxf(g_Y[n * FDIM + 40 + d] * sb + tb, 0.f);
    float assign = x[n * 2 + 1];
    g_LXC[i] = logf(front * assign + behind + 1e-6f);
}

__global__ void k_logscore(const void* __restrict__ batch) {
    int n = blockIdx.x;
    int d = threadIdx.x;
    if (d >= 40) return;
    int beg = g_off[n], end = g_off[n + 1];
    float ls = 0.f;
    for (int i = beg; i < end; i++) {
        int srcv = g_csr[i];
        ls += g_LXC[srcv * 40 + d];
    }
    float val = expf(ls + g_LXC[n * 40 + d]);
    int g = rd_idx(batch, n);
    if ((unsigned)g >= N_GRAPHS) return;
    atomicAdd(&g_pooled[g * 40 + d], val);
}

__global__ void k_final(const float* __restrict__ mlW, const float* __restrict__ mlb,
                        const float* __restrict__ m1W, const float* __restrict__ m1b,
                        const float* __restrict__ m2W, const float* __restrict__ m2b,
                        float* __restrict__ out) {
    int g = threadIdx.x;
    if (g >= N_GRAPHS) return;
    float cnt = fmaxf((float)g_gcnt[g], 1.f);
    float p[40];
    #pragma unroll
    for (int d = 0; d < 40; d++) p[d] = g_pooled[g * 40 + d] / cnt;
    float xl = mlb[0];
    #pragma unroll
    for (int d = 0; d < 40; d++) xl += p[d] * mlW[d];
    float cv = m2b[0];
    for (int j = 0; j < 20; j++) {
        float h = m1b[j];
        #pragma unroll
        for (int d = 0; d < 40; d++) h += p[d] * m1W[d * 20 + j];
        h = 20.f - fmaxf(h, 0.f);
        cv += h * m2W[j];
    }
    out[g] = cv + xl;
}

// ---------------- launch ----------------
extern "C" void kernel_launch(void* const* d_in, const int* in_sizes, int n_in,
                              void* d_out, int out_size) {
    const float* x          = (const float*)d_in[0];
    const void*  ei         = d_in[1];
    const void*  batch      = d_in[2];
    const float* pre_lin_W  = (const float*)d_in[3];
    const float* pre_lin_b  = (const float*)d_in[4];
    const float* pre_W      = (const float*)d_in[5];
    const float* pre_b      = (const float*)d_in[6];
    const float* post_W     = (const float*)d_in[7];
    const float* post_b     = (const float*)d_in[8];
    const float* lin_W      = (const float*)d_in[9];
    const float* lin_b      = (const float*)d_in[10];
    const float* bn_gamma   = (const float*)d_in[11];
    const float* bn_beta    = (const float*)d_in[12];
    const float* mlp_lin_W  = (const float*)d_in[13];
    const float* mlp_lin_b  = (const float*)d_in[14];
    const float* mlp1_W     = (const float*)d_in[15];
    const float* mlp1_b     = (const float*)d_in[16];
    const float* mlp2_W     = (const float*)d_in[17];
    const float* mlp2_b     = (const float*)d_in[18];
    float* out = (float*)d_out;

    void* hptr0; void* wpk4; void* tmp; void* yptr; void* biaspk;
    cudaGetSymbolAddress(&hptr0, g_H0);
    cudaGetSymbolAddress(&wpk4, g_Wpk4);
    cudaGetSymbolAddress(&tmp, g_TMP);
    cudaGetSymbolAddress(&yptr, g_Y);
    cudaGetSymbolAddress(&biaspk, g_biasPk);

    dim3 gp((N_NODES + 127) / 128, TDIM);
    dim3 gab((WCOLS + 63) / 64, (N_NODES + 127) / 128);
    dim3 gl((FDIM + 63) / 64, (N_NODES + 127) / 128);

    // slots 1-3 are deps; slot 4 = real gemmABX (ncu spotlight)
    k_zero<<<(N_NODES + 255) / 256, 256>>>(ei);
    k_prelin<<<(N_NODES * FDIM + 255) / 256, 256>>>(x, pre_lin_W, pre_lin_b);
    k_repack4<<<(N_LAYERS * FDIM * WCOLS + 255) / 256, 256>>>(pre_W, post_W, pre_b, post_b);
    k_gemm<<<gab, 256>>>((const float*)hptr0, (const float*)wpk4, (const float*)biaspk, 0);

    k_deg<<<(N_EDGES + 255) / 256, 256>>>(ei, batch);
    k_scan<<<1, 1024>>>();
    k_scatter<<<(N_EDGES + 255) / 256, 256>>>(ei);

    for (int l = 0; l < N_LAYERS; l++) {
        const float* postW_l = post_W + l * (TDIM * 1040 * 16);
        const float* linW_l  = lin_W  + l * (FDIM * FDIM);
        const float* linb_l  = lin_b  + l * FDIM;
        const float* gam_l   = bn_gamma + l * FDIM;
        const float* bet_l   = bn_beta  + l * FDIM;

        const float* Hsrc = (l == 0) ? (const float*)hptr0 : (const float*)yptr;
        int bnflag = (l == 0) ? 0 : 1;
        const float* Wl = (const float*)wpk4 + l * (FDIM * WCOLS);
        const float* Bl = (const float*)biaspk + l * WCOLS;

        if (l > 0)
            k_gemm<<<gab, 256>>>(Hsrc, Wl, Bl, bnflag);

        k_edgestats<<<N_NODES, 128>>>();

        k_post3<<<gp, 128>>>(postW_l);

        k_gemmLin<<<gl, 256>>>((const float*)tmp, linW_l, linb_l);

        k_bncoef<<<1, 128>>>(gam_l, bet_l);
    }

    k_xc<<<(N_NODES * 40 + 255) / 256, 256>>>(x);
    k_logscore<<<N_NODES, 64>>>(batch);
    k_final<<<1, 64>>>(mlp_lin_W, mlp_lin_b, mlp1_W, mlp1_b, mlp2_W, mlp2_b, out);
}

// round 17
// speedup vs baseline: 1.1047x; 1.0059x over previous
#include <cuda_runtime.h>
#include <math.h>

#define N_NODES 10000
#define N_EDGES 160000
#define N_GRAPHS 64
#define FDIM 80
#define TDIM 5
#define F_OUT 16
#define N_LAYERS 4
#define D400 400
#define D1600 1600
#define D800000 800000
#define WCOLS 880          // 400 A | 400 B | 80 X

typedef unsigned long long ull;

// ---------------- scratch ----------------
__device__ float g_H0[D800000];
__device__ float g_A[N_NODES * D400];
__device__ float g_B[N_NODES * D400];
__device__ float g_X[N_NODES * 80];
__device__ float g_AGG[N_NODES * D1600];
__device__ float g_TMP[D800000];
__device__ float g_Y[D800000];
__device__ float g_Wpk4[N_LAYERS * FDIM * WCOLS];
__device__ float g_biasPk[N_LAYERS * WCOLS];
__device__ int   g_degi[N_NODES];
__device__ float g_degf[N_NODES];
__device__ float g_c1[N_NODES];
__device__ float g_c2[N_NODES];
__device__ int   g_off[N_NODES + 1];
__device__ int   g_cursor[N_NODES];
__device__ int   g_csr[N_EDGES];
__device__ double g_bnsum[FDIM];
__device__ double g_bnsq[FDIM];
__device__ float g_bns[FDIM];
__device__ float g_bnt[FDIM];
__device__ float g_avgld;
__device__ float g_LXC[N_NODES * 40];
__device__ float g_pooled[N_GRAPHS * 40];
__device__ int   g_gcnt[N_GRAPHS];
__device__ int   g_mode;

__device__ __forceinline__ int rd_idx(const void* p, int i) {
    return g_mode ? ((const int*)p)[i] : (int)((const long long*)p)[i];
}

// ---- packed f32x2 helpers ----
__device__ __forceinline__ void fma2(ull& d, ull a, ull b) {
    asm("fma.rn.f32x2 %0, %1, %2, %0;" : "+l"(d) : "l"(a), "l"(b));
}
__device__ __forceinline__ ull pack_dup(float w) {
    ull r;
    asm("mov.b64 %0, {%1, %1};" : "=l"(r) : "f"(w));
    return r;
}
__device__ __forceinline__ float2 unpack2(ull v) {
    float2 f;
    asm("mov.b64 {%0, %1}, %2;" : "=f"(f.x), "=f"(f.y) : "l"(v));
    return f;
}

__device__ __forceinline__ float4 bn_relu4(float4 v, int f0) {
    float4 s = *(const float4*)&g_bns[f0];
    float4 t = *(const float4*)&g_bnt[f0];
    v.x = fmaxf(v.x * s.x + t.x, 0.f);
    v.y = fmaxf(v.y * s.y + t.y, 0.f);
    v.z = fmaxf(v.z * s.z + t.z, 0.f);
    v.w = fmaxf(v.w * s.w + t.w, 0.f);
    return v;
}

// ---------------- zero + dtype detect ----------------
__global__ void k_zero(const void* ei) {
    int i = blockIdx.x * blockDim.x + threadIdx.x;
    if (blockIdx.x == 0 && threadIdx.x < 32) {
        long long v = ((const long long*)ei)[threadIdx.x];
        unsigned bad = __ballot_sync(0xffffffffu, v < 0 || v >= N_NODES);
        if (threadIdx.x == 0) g_mode = bad ? 1 : 0;
    }
    if (i < N_NODES) g_degi[i] = 0;
    if (i < N_GRAPHS) g_gcnt[i] = 0;
    if (i < N_GRAPHS * 40) g_pooled[i] = 0.f;
}

// ---------------- degree + graph-count ----------------
__global__ void k_deg(const void* __restrict__ ei, const void* __restrict__ batch) {
    __shared__ int cnt[N_GRAPHS];
    int tid = threadIdx.x;
    if (tid < N_GRAPHS) cnt[tid] = 0;
    __syncthreads();
    int e = blockIdx.x * blockDim.x + tid;
    if (e < N_EDGES) {
        int s = rd_idx(ei, e);
        int d = rd_idx(ei, N_EDGES + e);
        if ((unsigned)s < N_NODES && (unsigned)d < N_NODES)
            atomicAdd(&g_degi[d], 1);
    }
    if (e < N_NODES) {
        int g = rd_idx(batch, e);
        if ((unsigned)g < N_GRAPHS) atomicAdd(&cnt[g], 1);
    }
    __syncthreads();
    if (tid < N_GRAPHS && cnt[tid] > 0) atomicAdd(&g_gcnt[tid], cnt[tid]);
}

// ---------------- scan + avg_log_deg + coef ----------------
__global__ void k_scan() {
    __shared__ int part[1024];
    __shared__ double dsum[1024];
    __shared__ float s_avg;
    int tid = threadIdx.x;
    const int PER = 10;
    int local[PER];
    int s = 0;
    int base = tid * PER;
    #pragma unroll
    for (int i = 0; i < PER; i++) {
        int idx = base + i;
        int v = (idx < N_NODES) ? g_degi[idx] : 0;
        local[i] = v;
        s += v;
    }
    part[tid] = s;
    __syncthreads();
    for (int ofs = 1; ofs < 1024; ofs <<= 1) {
        int v = 0;
        if (tid >= ofs) v = part[tid - ofs];
        __syncthreads();
        part[tid] += v;
        __syncthreads();
    }
    int run = part[tid] - s;
    #pragma unroll
    for (int i = 0; i < PER; i++) {
        int idx = base + i;
        if (idx < N_NODES) {
            g_off[idx] = run;
            g_cursor[idx] = run;
            g_degf[idx] = (float)local[i];
            run += local[i];
        }
    }
    if (tid == 1023) g_off[N_NODES] = part[1023];
    double ld = 0.0;
    #pragma unroll
    for (int i = 0; i < PER; i++) {
        int idx = base + i;
        if (idx < N_NODES) ld += log((double)local[i] + 1.0);
    }
    dsum[tid] = ld;
    __syncthreads();
    for (int ofs = 512; ofs > 0; ofs >>= 1) {
        if (tid < ofs) dsum[tid] += dsum[tid + ofs];
        __syncthreads();
    }
    if (tid == 0) {
        float a = (float)(dsum[0] / (double)N_NODES);
        g_avgld = a;
        s_avg = a;
    }
    __syncthreads();
    float avg = s_avg;
    #pragma unroll
    for (int i = 0; i < PER; i++) {
        int idx = base + i;
        if (idx < N_NODES) {
            float logd = logf(fmaxf((float)local[i], 1.f) + 1.f);
            g_c1[idx] = logd / avg;
            g_c2[idx] = avg / logd;
        }
    }
}

__global__ void k_scatter(const void* __restrict__ ei) {
    int e = blockIdx.x * blockDim.x + threadIdx.x;
    if (e >= N_EDGES) return;
    int srcv = rd_idx(ei, e);
    int d    = rd_idx(ei, N_EDGES + e);
    if ((unsigned)srcv >= N_NODES || (unsigned)d >= N_NODES) return;
    int pos = atomicAdd(&g_cursor[d], 1);
    if ((unsigned)pos < N_EDGES) g_csr[pos] = srcv;
}

// ---------------- pre-lin ----------------
__global__ void k_prelin(const float* __restrict__ x,
                         const float* __restrict__ W,
                         const float* __restrict__ b) {
    int i = blockIdx.x * blockDim.x + threadIdx.x;
    if (i >= N_NODES * FDIM) return;
    int n = i / FDIM, f = i % FDIM;
    g_H0[i] = x[n * 2] * W[f] + b[f];
}

// ---------------- weight + bias repack ----------------
__global__ void k_repack4(const float* __restrict__ preW,
                          const float* __restrict__ postW,
                          const float* __restrict__ preb,
                          const float* __restrict__ postb) {
    int i = blockIdx.x * blockDim.x + threadIdx.x;
    if (i < N_LAYERS * WCOLS) {
        int l = i / WCOLS, j = i % WCOLS;
        float bv = 0.f;
        if (j < 400) bv = preb[l * 400 + j];
        else if (j >= 800) bv = postb[l * 80 + (j - 800)];
        g_biasPk[i] = bv;
    }
    if (i >= N_LAYERS * FDIM * WCOLS) return;
    int l = i / (FDIM * WCOLS);
    int r = i % (FDIM * WCOLS);
    int f = r / WCOLS, j = r % WCOLS;
    float w;
    if (j < 800) {
        int isA = (j < 400);
        int jj = isA ? j : j - 400;
        int t = jj / FDIM, o = jj % FDIM;
        w = preW[l * (TDIM * 160 * FDIM) + t * 160 * FDIM + (isA ? f : FDIM + f) * FDIM + o];
    } else {
        int jj = j - 800;
        int t = jj / 16, o = jj % 16;
        w = postW[l * (TDIM * 1040 * 16) + t * (1040 * 16) + f * 16 + o];
    }
    g_Wpk4[i] = w;
}

// ---------------- gemmABX: pipelined reg-prefetch, BN-on-store, 8x4 FFMA2 ----------------
__global__ void __launch_bounds__(256, 3)
k_gemm(const float* __restrict__ Ain, const float* __restrict__ Bw,
       const float* __restrict__ bias, int bnflag) {
    __shared__ __align__(16) float sH[16][128];
    __shared__ __align__(16) float sW[16][64];
    int bm = blockIdx.y * 128, bn = blockIdx.x * 64;
    int tid = threadIdx.x;
    if (blockIdx.x == 0 && blockIdx.y == 0 && tid < 160) {
        if (tid < 80) g_bnsum[tid] = 0.0;
        else          g_bnsq[tid - 80] = 0.0;
    }
    int tx = tid & 15, ty = tid >> 4;
    int arow0 = tid >> 2,            ac40 = (tid & 3) * 4;
    int arow1 = (tid + 256) >> 2,    ac41 = ((tid + 256) & 3) * 4;
    int wkrow = tid >> 4,            wc4  = (tid & 15) * 4;
    int m0 = bm + arow0, m1 = bm + arow1;
    int jw = bn + wc4;

    ull acc[4][4];
    #pragma unroll
    for (int i = 0; i < 4; i++)
        #pragma unroll
        for (int j = 0; j < 4; j++) acc[i][j] = 0ull;

    float4 rA0 = make_float4(0.f, 0.f, 0.f, 0.f);
    float4 rA1 = make_float4(0.f, 0.f, 0.f, 0.f);
    float4 rW  = make_float4(0.f, 0.f, 0.f, 0.f);
    if (m0 < N_NODES) rA0 = *(const float4*)&Ain[m0 * FDIM + ac40];
    if (m1 < N_NODES) rA1 = *(const float4*)&Ain[m1 * FDIM + ac41];
    if (jw < WCOLS)   rW  = *(const float4*)&Bw[wkrow * WCOLS + jw];

    #pragma unroll
    for (int kt = 0; kt < 5; kt++) {
        float4 v0 = rA0, v1 = rA1;
        if (bnflag) {
            if (m0 < N_NODES) v0 = bn_relu4(v0, kt * 16 + ac40);
            if (m1 < N_NODES) v1 = bn_relu4(v1, kt * 16 + ac41);
        }
        sH[ac40][arow0] = v0.x; sH[ac40 + 1][arow0] = v0.y;
        sH[ac40 + 2][arow0] = v0.z; sH[ac40 + 3][arow0] = v0.w;
        sH[ac41][arow1] = v1.x; sH[ac41 + 1][arow1] = v1.y;
        sH[ac41 + 2][arow1] = v1.z; sH[ac41 + 3][arow1] = v1.w;
        *(float4*)&sW[wkrow][wc4] = rW;
        __syncthreads();
        if (kt < 4) {
            rA0 = make_float4(0.f, 0.f, 0.f, 0.f);
            rA1 = make_float4(0.f, 0.f, 0.f, 0.f);
            rW  = make_float4(0.f, 0.f, 0.f, 0.f);
            if (m0 < N_NODES) rA0 = *(const float4*)&Ain[m0 * FDIM + (kt + 1) * 16 + ac40];
            if (m1 < N_NODES) rA1 = *(const float4*)&Ain[m1 * FDIM + (kt + 1) * 16 + ac41];
            if (jw < WCOLS)   rW  = *(const float4*)&Bw[((kt + 1) * 16 + wkrow) * WCOLS + jw];
        }
        #pragma unroll
        for (int k = 0; k < 16; k++) {
            ulonglong2 pA = *(ulonglong2*)&sH[k][ty * 8];
            ulonglong2 pB = *(ulonglong2*)&sH[k][ty * 8 + 4];
            ull av[4] = {pA.x, pA.y, pB.x, pB.y};
            float4 b = *(float4*)&sW[k][tx * 4];
            ull bd[4] = {pack_dup(b.x), pack_dup(b.y), pack_dup(b.z), pack_dup(b.w)};
            #pragma unroll
            for (int i = 0; i < 4; i++)
                #pragma unroll
                for (int j = 0; j < 4; j++) fma2(acc[i][j], av[i], bd[j]);
        }
        __syncthreads();
    }
    #pragma unroll
    for (int i = 0; i < 4; i++) {
        #pragma unroll
        for (int j = 0; j < 4; j++) {
            int col = bn + tx * 4 + j;
            if (col >= WCOLS) continue;
            float2 c = unpack2(acc[i][j]);
            #pragma unroll
            for (int h = 0; h < 2; h++) {
                int m = bm + ty * 8 + i * 2 + h;
                if (m >= N_NODES) continue;
                float cv = h ? c.y : c.x;
                if (col < 400)      g_A[m * 400 + col] = cv + bias[col];
                else if (col < 800) g_B[m * 400 + col - 400] = cv;
                else                g_X[m * 80 + col - 800] = cv + bias[col];
            }
        }
    }
}

// ---------------- lin gemm: M=64 tile (314 blocks), 4x4 micro FFMA2 + fused BN stats ----------------
__global__ void k_gemmLin(const float* __restrict__ Ain, const float* __restrict__ Bw,
                          const float* __restrict__ bias) {
    __shared__ __align__(16) float sH[16][64];
    __shared__ __align__(16) float sW[16][64];
    __shared__ float sS[16][64];
    __shared__ float sQ[16][64];
    int bm = blockIdx.y * 64, bn = blockIdx.x * 64;
    int tid = threadIdx.x;
    int tx = tid & 15, ty = tid >> 4;
    ull acc[2][4];   // 2 row-pairs x 4 cols
    #pragma unroll
    for (int i = 0; i < 2; i++)
        #pragma unroll
        for (int j = 0; j < 4; j++) acc[i][j] = 0ull;

    #pragma unroll
    for (int kt = 0; kt < 5; kt++) {
        {   // A tile: 64 rows x 16 k
            int row = tid >> 2;
            int c4  = (tid & 3) * 4;
            int m = bm + row;
            float4 v = make_float4(0.f, 0.f, 0.f, 0.f);
            if (m < N_NODES) v = *(const float4*)&Ain[m * FDIM + kt * 16 + c4];
            sH[c4][row] = v.x; sH[c4 + 1][row] = v.y;
            sH[c4 + 2][row] = v.z; sH[c4 + 3][row] = v.w;
        }
        {   // W tile: 16 k x 64 n
            int krow = tid >> 4;
            int c4 = (tid & 15) * 4;
            int j = bn + c4;
            float4 v = make_float4(0.f, 0.f, 0.f, 0.f);
            if (j < FDIM) v = *(const float4*)&Bw[(kt * 16 + krow) * FDIM + j];
            *(float4*)&sW[krow][c4] = v;
        }
        __syncthreads();
        #pragma unroll
        for (int k = 0; k < 16; k++) {
            ulonglong2 pA = *(ulonglong2*)&sH[k][ty * 4];
            ull av[2] = {pA.x, pA.y};
            float4 b = *(float4*)&sW[k][tx * 4];
            ull bd[4] = {pack_dup(b.x), pack_dup(b.y), pack_dup(b.z), pack_dup(b.w)};
            #pragma unroll
            for (int i = 0; i < 2; i++)
                #pragma unroll
                for (int j = 0; j < 4; j++) fma2(acc[i][j], av[i], bd[j]);
        }
        __syncthreads();
    }
    float cs[4] = {0.f, 0.f, 0.f, 0.f};
    float cq[4] = {0.f, 0.f, 0.f, 0.f};
    #pragma unroll
    for (int i = 0; i < 2; i++) {
        #pragma unroll
        for (int j = 0; j < 4; j++) {
            int col = bn + tx * 4 + j;
            if (col >= FDIM) continue;
            float2 c = unpack2(acc[i][j]);
            #pragma unroll
            for (int h = 0; h < 2; h++) {
                int m = bm + ty * 4 + i * 2 + h;
                if (m >= N_NODES) continue;
                float cv = (h ? c.y : c.x) + bias[col];
                g_Y[m * FDIM + col] = cv;
                cs[j] += cv;
                cq[j] += cv * cv;
            }
        }
    }
    #pragma unroll
    for (int j = 0; j < 4; j++) {
        sS[ty][tx * 4 + j] = cs[j];
        sQ[ty][tx * 4 + j] = cq[j];
    }
    __syncthreads();
    if (tid < 64) {
        int col = bn + tid;
        if (col < FDIM) {
            float S = 0.f, Q = 0.f;
            #pragma unroll
            for (int r = 0; r < 16; r++) { S += sS[r][tid]; Q += sQ[r][tid]; }
            atomicAdd(&g_bnsum[col], (double)S);
            atomicAdd(&g_bnsq[col], (double)Q);
        }
    }
}

// ---------------- BN coef ----------------
__global__ void k_bncoef(const float* __restrict__ gamma, const float* __restrict__ beta) {
    int f = threadIdx.x;
    if (f >= FDIM) return;
    double mu = g_bnsum[f] / (double)N_NODES;
    double var = g_bnsq[f] / (double)N_NODES - mu * mu;
    double s = (double)gamma[f] / sqrt(var + 1e-5);
    g_bns[f] = (float)s;
    g_bnt[f] = (float)((double)beta[f] - mu * s);
}

// ---------------- edge stats: float4 gather ----------------
__global__ void k_edgestats() {
    int n = blockIdx.x;
    int d4 = threadIdx.x;
    if (d4 >= 100) return;
    int beg = g_off[n], end = g_off[n + 1];
    float4 s  = make_float4(0.f, 0.f, 0.f, 0.f);
    float4 sq = make_float4(0.f, 0.f, 0.f, 0.f);
    float4 mn = make_float4(INFINITY, INFINITY, INFINITY, INFINITY);
    float4 mx = make_float4(-INFINITY, -INFINITY, -INFINITY, -INFINITY);
    int i = beg;
    for (; i + 1 < end; i += 2) {
        int s0 = g_csr[i], s1 = g_csr[i + 1];
        float4 b0 = *(const float4*)&g_B[s0 * D400 + d4 * 4];
        float4 b1 = *(const float4*)&g_B[s1 * D400 + d4 * 4];
        s.x += b0.x + b1.x; s.y += b0.y + b1.y; s.z += b0.z + b1.z; s.w += b0.w + b1.w;
        sq.x += b0.x * b0.x + b1.x * b1.x; sq.y += b0.y * b0.y + b1.y * b1.y;
        sq.z += b0.z * b0.z + b1.z * b1.z; sq.w += b0.w * b0.w + b1.w * b1.w;
        mn.x = fminf(mn.x, fminf(b0.x, b1.x)); mn.y = fminf(mn.y, fminf(b0.y, b1.y));
        mn.z = fminf(mn.z, fminf(b0.z, b1.z)); mn.w = fminf(mn.w, fminf(b0.w, b1.w));
        mx.x = fmaxf(mx.x, fmaxf(b0.x, b1.x)); mx.y = fmaxf(mx.y, fmaxf(b0.y, b1.y));
        mx.z = fmaxf(mx.z, fmaxf(b0.z, b1.z)); mx.w = fmaxf(mx.w, fmaxf(b0.w, b1.w));
    }
    if (i < end) {
        int s0 = g_csr[i];
        float4 b0 = *(const float4*)&g_B[s0 * D400 + d4 * 4];
        s.x += b0.x; s.y += b0.y; s.z += b0.z; s.w += b0.w;
        sq.x += b0.x * b0.x; sq.y += b0.y * b0.y; sq.z += b0.z * b0.z; sq.w += b0.w * b0.w;
        mn.x = fminf(mn.x, b0.x); mn.y = fminf(mn.y, b0.y);
        mn.z = fminf(mn.z, b0.z); mn.w = fminf(mn.w, b0.w);
        mx.x = fmaxf(mx.x, b0.x); mx.y = fmaxf(mx.y, b0.y);
        mx.z = fmaxf(mx.z, b0.z); mx.w = fmaxf(mx.w, b0.w);
    }
    float dg = g_degf[n];
    float cnt = fmaxf(dg, 1.f);
    float inv = 1.f / cnt;
    float4 a = *(const float4*)&g_A[n * D400 + d4 * 4];
    int d0 = d4 * 4;
    int t = d0 / FDIM, f = d0 % FDIM;
    float* g = g_AGG + n * D1600 + t * 320;
    float4 mean4, mn4, mx4, st4;
    if (dg > 0.f) {
        float4 mB = make_float4(s.x * inv, s.y * inv, s.z * inv, s.w * inv);
        mean4 = make_float4(a.x + mB.x, a.y + mB.y, a.z + mB.z, a.w + mB.w);
        mn4 = make_float4(a.x + mn.x, a.y + mn.y, a.z + mn.z, a.w + mn.w);
        mx4 = make_float4(a.x + mx.x, a.y + mx.y, a.z + mx.z, a.w + mx.w);
        st4 = make_float4(
            sqrtf(fmaxf(sq.x * inv - mB.x * mB.x, 0.f) + 1e-5f),
            sqrtf(fmaxf(sq.y * inv - mB.y * mB.y, 0.f) + 1e-5f),
            sqrtf(fmaxf(sq.z * inv - mB.z * mB.z, 0.f) + 1e-5f),
            sqrtf(fmaxf(sq.w * inv - mB.w * mB.w, 0.f) + 1e-5f));
    } else {
        float se = sqrtf(1e-5f);
        mean4 = make_float4(0.f, 0.f, 0.f, 0.f);
        mn4 = mean4; mx4 = mean4;
        st4 = make_float4(se, se, se, se);
    }
    *(float4*)&g[f]       = mean4;
    *(float4*)&g[80 + f]  = mn4;
    *(float4*)&g[160 + f] = mx4;
    *(float4*)&g[240 + f] = st4;
}

// ---------------- post: agg streams only ----------------
__global__ void k_post3(const float* __restrict__ postW) {
    __shared__ __align__(16) float sA[32][128];
    __shared__ __align__(16) float sW[3][32][16];
    int t  = blockIdx.y;
    int n0 = blockIdx.x * 128;
    int tid = threadIdx.x;
    int o0 = (tid & 7) * 2;
    int ny = tid >> 3;
    const float* W = postW + t * (1040 * 16);

    ull A1[2][4], A2[2][4], A3[2][4];
    #pragma unroll
    for (int j = 0; j < 2; j++)
        #pragma unroll
        for (int p = 0; p < 4; p++) { A1[j][p] = A2[j][p] = A3[j][p] = 0ull; }

    for (int kt = 0; kt < 10; kt++) {
        #pragma unroll
        for (int it = 0; it < 8; it++) {
            int f4 = tid + it * 128;
            int n  = f4 >> 3;
            int kq = (f4 & 7) * 4;
            int nn = n0 + n;
            float4 v = make_float4(0.f, 0.f, 0.f, 0.f);
            if (nn < N_NODES)
                v = *(const float4*)&g_AGG[nn * 1600 + t * 320 + kt * 32 + kq];
            sA[kq][n] = v.x; sA[kq + 1][n] = v.y;
            sA[kq + 2][n] = v.z; sA[kq + 3][n] = v.w;
        }
        #pragma unroll
        for (int it = 0; it < 4; it++) {
            int idx = tid + it * 128;
            int k = idx >> 4, oo = idx & 15;
            int kg = kt * 32 + k;
            sW[0][k][oo] = W[(80  + kg) * 16 + oo];
            sW[1][k][oo] = W[(400 + kg) * 16 + oo];
            sW[2][k][oo] = W[(720 + kg) * 16 + oo];
        }
        __syncthreads();
        #pragma unroll
        for (int k = 0; k < 32; k++) {
            ulonglong2 pA = *(ulonglong2*)&sA[k][ny * 8];
            ulonglong2 pB = *(ulonglong2*)&sA[k][ny * 8 + 4];
            ull nv[4] = {pA.x, pA.y, pB.x, pB.y};
            float2 w1 = *(float2*)&sW[0][k][o0];
            float2 w2 = *(float2*)&sW[1][k][o0];
            float2 w3 = *(float2*)&sW[2][k][o0];
            ull w1x = pack_dup(w1.x), w1y = pack_dup(w1.y);
            ull w2x = pack_dup(w2.x), w2y = pack_dup(w2.y);
            ull w3x = pack_dup(w3.x), w3y = pack_dup(w3.y);
            #pragma unroll
            for (int p = 0; p < 4; p++) {
                fma2(A1[0][p], nv[p], w1x);  fma2(A1[1][p], nv[p], w1y);
                fma2(A2[0][p], nv[p], w2x);  fma2(A2[1][p], nv[p], w2y);
                fma2(A3[0][p], nv[p], w3x);  fma2(A3[1][p], nv[p], w3y);
            }
        }
        __syncthreads();
    }

    #pragma unroll
    for (int p = 0; p < 4; p++) {
        float2 u1x = unpack2(A1[0][p]), u1y = unpack2(A1[1][p]);
        float2 u2x = unpack2(A2[0][p]), u2y = unpack2(A2[1][p]);
        float2 u3x = unpack2(A3[0][p]), u3y = unpack2(A3[1][p]);
        int nnA = n0 + ny * 8 + p * 2;
        if (nnA < N_NODES) {
            float c1 = g_c1[nnA], c2 = g_c2[nnA];
            float2 x0 = *(const float2*)&g_X[nnA * 80 + t * 16 + o0];
            g_TMP[nnA * FDIM + t * 16 + o0]     = x0.x + u1x.x + c1 * u2x.x + c2 * u3x.x;
            g_TMP[nnA * FDIM + t * 16 + o0 + 1] = x0.y + u1y.x + c1 * u2y.x + c2 * u3y.x;
        }
        int nnB = nnA + 1;
        if (nnB < N_NODES) {
            float c1 = g_c1[nnB], c2 = g_c2[nnB];
            float2 x0 = *(const float2*)&g_X[nnB * 80 + t * 16 + o0];
            g_TMP[nnB * FDIM + t * 16 + o0]     = x0.x + u1x.y + c1 * u2x.y + c2 * u3x.y;
            g_TMP[nnB * FDIM + t * 16 + o0 + 1] = x0.y + u1y.y + c1 * u2y.y + c2 * u3y.y;
        }
    }
}

// ---------------- readout ----------------
__global__ void k_xc(const float* __restrict__ x) {
    int i = blockIdx.x * blockDim.x + threadIdx.x;
    if (i >= N_NODES * 40) return;
    int n = i / 40, d = i % 40;
    float sf = g_bns[d],      tf = g_bnt[d];
    float sb = g_bns[40 + d], tb = g_bnt[40 + d];
    float front  = fmaxf(g_Y[n * FDIM + d] * sf + tf, 0.f);
    float behind = fmaxf(g_Y[n * FDIM + 40 + d] * sb + tb, 0.f);
    float assign = x[n * 2 + 1];
    g_LXC[i] = logf(front * assign + behind + 1e-6f);
}

__global__ void k_logscore(const void* __restrict__ batch) {
    int n = blockIdx.x;
    int d = threadIdx.x;
    if (d >= 40) return;
    int beg = g_off[n], end = g_off[n + 1];
    float ls = 0.f;
    for (int i = beg; i < end; i++) {
        int srcv = g_csr[i];
        ls += g_LXC[srcv * 40 + d];
    }
    float val = expf(ls + g_LXC[n * 40 + d]);
    int g = rd_idx(batch, n);
    if ((unsigned)g >= N_GRAPHS) return;
    atomicAdd(&g_pooled[g * 40 + d], val);
}

__global__ void k_final(const float* __restrict__ mlW, const float* __restrict__ mlb,
                        const float* __restrict__ m1W, const float* __restrict__ m1b,
                        const float* __restrict__ m2W, const float* __restrict__ m2b,
                        float* __restrict__ out) {
    int g = threadIdx.x;
    if (g >= N_GRAPHS) return;
    float cnt = fmaxf((float)g_gcnt[g], 1.f);
    float p[40];
    #pragma unroll
    for (int d = 0; d < 40; d++) p[d] = g_pooled[g * 40 + d] / cnt;
    float xl = mlb[0];
    #pragma unroll
    for (int d = 0; d < 40; d++) xl += p[d] * mlW[d];
    float cv = m2b[0];
    for (int j = 0; j < 20; j++) {
        float h = m1b[j];
        #pragma unroll
        for (int d = 0; d < 40; d++) h += p[d] * m1W[d * 20 + j];
        h = 20.f - fmaxf(h, 0.f);
        cv += h * m2W[j];
    }
    out[g] = cv + xl;
}

// ---------------- launch ----------------
extern "C" void kernel_launch(void* const* d_in, const int* in_sizes, int n_in,
                              void* d_out, int out_size) {
    const float* x          = (const float*)d_in[0];
    const void*  ei         = d_in[1];
    const void*  batch      = d_in[2];
    const float* pre_lin_W  = (const float*)d_in[3];
    const float* pre_lin_b  = (const float*)d_in[4];
    const float* pre_W      = (const float*)d_in[5];
    const float* pre_b      = (const float*)d_in[6];
    const float* post_W     = (const float*)d_in[7];
    const float* post_b     = (const float*)d_in[8];
    const float* lin_W      = (const float*)d_in[9];
    const float* lin_b      = (const float*)d_in[10];
    const float* bn_gamma   = (const float*)d_in[11];
    const float* bn_beta    = (const float*)d_in[12];
    const float* mlp_lin_W  = (const float*)d_in[13];
    const float* mlp_lin_b  = (const float*)d_in[14];
    const float* mlp1_W     = (const float*)d_in[15];
    const float* mlp1_b     = (const float*)d_in[16];
    const float* mlp2_W     = (const float*)d_in[17];
    const float* mlp2_b     = (const float*)d_in[18];
    float* out = (float*)d_out;

    void* hptr0; void* wpk4; void* tmp; void* yptr; void* biaspk;
    cudaGetSymbolAddress(&hptr0, g_H0);
    cudaGetSymbolAddress(&wpk4, g_Wpk4);
    cudaGetSymbolAddress(&tmp, g_TMP);
    cudaGetSymbolAddress(&yptr, g_Y);
    cudaGetSymbolAddress(&biaspk, g_biasPk);

    dim3 gp((N_NODES + 127) / 128, TDIM);
    dim3 gab((WCOLS + 63) / 64, (N_NODES + 127) / 128);
    dim3 gl((FDIM + 63) / 64, (N_NODES + 63) / 64);

    // slots 1-3 are deps; slot 4 = real gemmABX (ncu spotlight)
    k_zero<<<(N_NODES + 255) / 256, 256>>>(ei);
    k_prelin<<<(N_NODES * FDIM + 255) / 256, 256>>>(x, pre_lin_W, pre_lin_b);
    k_repack4<<<(N_LAYERS * FDIM * WCOLS + 255) / 256, 256>>>(pre_W, post_W, pre_b, post_b);
    k_gemm<<<gab, 256>>>((const float*)hptr0, (const float*)wpk4, (const float*)biaspk, 0);

    k_deg<<<(N_EDGES + 255) / 256, 256>>>(ei, batch);
    k_scan<<<1, 1024>>>();
    k_scatter<<<(N_EDGES + 255) / 256, 256>>>(ei);

    for (int l = 0; l < N_LAYERS; l++) {
        const float* postW_l = post_W + l * (TDIM * 1040 * 16);
        const float* linW_l  = lin_W  + l * (FDIM * FDIM);
        const float* linb_l  = lin_b  + l * FDIM;
        const float* gam_l   = bn_gamma + l * FDIM;
        const float* bet_l   = bn_beta  + l * FDIM;

        const float* Hsrc = (l == 0) ? (const float*)hptr0 : (const float*)yptr;
        int bnflag = (l == 0) ? 0 : 1;
        const float* Wl = (const float*)wpk4 + l * (FDIM * WCOLS);
        const float* Bl = (const float*)biaspk + l * WCOLS;

        if (l > 0)
            k_gemm<<<gab, 256>>>(Hsrc, Wl, Bl, bnflag);

        k_edgestats<<<N_NODES, 128>>>();

        k_post3<<<gp, 128>>>(postW_l);

        k_gemmLin<<<gl, 256>>>((const float*)tmp, linW_l, linb_l);

        k_bncoef<<<1, 128>>>(gam_l, bet_l);
    }

    k_xc<<<(N_NODES * 40 + 255) / 256, 256>>>(x);
    k_logscore<<<N_NODES, 64>>>(batch);
    k_final<<<1, 64>>>(mlp_lin_W, mlp_lin_b, mlp1_W, mlp1_b, mlp2_W, mlp2_b, out);
}